// round 12
// baseline (speedup 1.0000x reference)
#include <cuda_runtime.h>
#include <cuda_fp16.h>
#include <cstdint>

// ===========================================================================
// VQPatchEncoder — single-term fp16 mma.sync GEMM + DELTA-certified exact
// argmax. R12: GEMM split into 4 N-groups per M-tile (grid 512x4 = 2048
// small CTAs) to kill the 2-wave quantization loss; per-group top-2
// partials merged by a combine kernel (ascending-group first-occurrence).
// Mainloop / rescore / tail unchanged from R11.
// ===========================================================================

#define BATCH 1024
#define NP    64
#define PD    192
#define KC    4096
#define ED    2048
#define VD    2048
#define MROWS (BATCH * NP)      // 65536
#define BM    128
#define BN    64
#define NGROUP 4
#define NT_G   16                // N-tiles per group
#define KSTEPS (PD / 16)         // 12
#define AROWB  (PD * 2)          // 384
#define ASMEM  (BM * AROWB)      // 49152
#define BBUF   (PD * BN * 2)     // 24576 (full-K tile)
#define MBAR_OFF (ASMEM + 2 * BBUF)           // 98304
#define GEMM_SMEM (MBAR_OFF + 32)             // 98336
#define GEMM_THREADS 256
#define DELTA 4e-3f

// ---- device-global scratch ------------------------------------------------
__device__ __align__(16) __half g_bsw[(size_t)PD * KC];   // per-tile smem images
__device__ int    g_indices[MROWS];
__device__ int    g_flagged[MROWS];
__device__ int    g_nflag;
__device__ float  g_pv1[(size_t)MROWS * NGROUP];   // GEMM group partials
__device__ float  g_pv2[(size_t)MROWS * NGROUP];
__device__ int    g_pi1[(size_t)MROWS * NGROUP];
__device__ float  g_part_val[(size_t)MROWS * 4];   // rescore partials (reused after combine)
__device__ int    g_part_idx[(size_t)MROWS * 4];

__device__ __forceinline__ uint32_t smem_u32(const void* p) {
    uint32_t a;
    asm("{ .reg .u64 t; cvta.to.shared.u64 t, %1; cvt.u32.u64 %0, t; }"
        : "=r"(a) : "l"(p));
    return a;
}

#define MBARRIER_INIT(mbar, cnt) \
    asm volatile("mbarrier.init.shared.b64 [%0], %1;" \
                 :: "r"((uint32_t)(mbar)), "r"((uint32_t)(cnt)) : "memory")
#define MBARRIER_EXPECT_TX(mbar, bytes) \
    asm volatile("mbarrier.arrive.expect_tx.shared.b64 _, [%0], %1;" \
                 :: "r"((uint32_t)(mbar)), "r"((uint32_t)(bytes)) : "memory")

#define MBARRIER_WAIT_PARITY(mbar_addr, phase_parity) do {                        \
    uint32_t _mbar = (uint32_t)(mbar_addr);                                       \
    uint32_t _par  = (uint32_t)(phase_parity);                                    \
    uint32_t _done;                                                               \
    asm volatile("{\n\t.reg .pred p;\n\t"                                         \
        "mbarrier.try_wait.parity.acquire.cta.shared::cta.b64 p, [%1], %2;\n\t"   \
        "selp.b32 %0, 1, 0, p;\n\t}"                                              \
        : "=r"(_done) : "r"(_mbar), "r"(_par) : "memory");                        \
    if (!_done) {                                                                 \
        asm volatile("{\n\t.reg .pred P1;\n\t"                                    \
            "WAIT_LOOP_%=:\n\t"                                                   \
            "mbarrier.try_wait.parity.acquire.cta.shared::cta.b64 P1, [%0], %1, 0x989680;\n\t" \
            "@P1 bra.uni WAIT_DONE_%=;\n\t"                                       \
            "bra.uni WAIT_LOOP_%=;\n\t"                                           \
            "WAIT_DONE_%=:\n\t}"                                                  \
            :: "r"(_mbar), "r"(_par) : "memory");                                 \
    }                                                                             \
} while (0)

__device__ __forceinline__ void bulk_cp(uint32_t dst, const void* src,
                                        uint32_t bytes, uint32_t mbar) {
    asm volatile(
        "cp.async.bulk.shared::cta.global.mbarrier::complete_tx::bytes "
        "[%0], [%1], %2, [%3];"
        :: "r"(dst), "l"(src), "r"(bytes), "r"(mbar) : "memory");
}

__device__ __forceinline__ void ldsm4(uint32_t* r, uint32_t addr) {
    asm volatile("ldmatrix.sync.aligned.m8n8.x4.shared.b16 {%0,%1,%2,%3}, [%4];"
                 : "=r"(r[0]), "=r"(r[1]), "=r"(r[2]), "=r"(r[3]) : "r"(addr));
}
__device__ __forceinline__ void ldsm4t(uint32_t* r, uint32_t addr) {
    asm volatile("ldmatrix.sync.aligned.m8n8.x4.trans.shared.b16 {%0,%1,%2,%3}, [%4];"
                 : "=r"(r[0]), "=r"(r[1]), "=r"(r[2]), "=r"(r[3]) : "r"(addr));
}
__device__ __forceinline__ void mma16816(float* c, const uint32_t* a,
                                         uint32_t b0, uint32_t b1) {
    asm volatile(
        "mma.sync.aligned.m16n8k16.row.col.f32.f16.f16.f32 "
        "{%0,%1,%2,%3}, {%4,%5,%6,%7}, {%8,%9}, {%0,%1,%2,%3};"
        : "+f"(c[0]), "+f"(c[1]), "+f"(c[2]), "+f"(c[3])
        : "r"(a[0]), "r"(a[1]), "r"(a[2]), "r"(a[3]), "r"(b0), "r"(b1));
}

// ===========================================================================
// 1) Prep: codebook smem-image layout + flag reset only.
// ===========================================================================
#define CB_BLOCKS  ((PD * KC) / 256)             // 3072
__global__ void prep_kernel(const float* __restrict__ cbk) {
    int bid = blockIdx.x;
    if (bid < CB_BLOCKS) {
        int idx = bid * 256 + threadIdx.x;
        int n = idx % KC;
        int d = idx / KC;
        int t = n >> 6, nt = n & 63;
        int kc = d >> 6, r = d & 63;
        int g = nt >> 3;
        size_t half_off = (size_t)(t * 3 + kc) * 4096
                        + r * 64 + ((g ^ (r & 7)) * 8) + (nt & 7);
        g_bsw[half_off] = __float2half_rn(cbk[(size_t)n * PD + d]);
    } else {
        if (threadIdx.x == 0) g_nflag = 0;
    }
}

// ===========================================================================
// 2) fp16 mma.sync GEMM, one (M-tile, N-group) per CTA. Writes per-group
//    top-2 partials. Grid (512, 4).
// ===========================================================================
__global__ __launch_bounds__(GEMM_THREADS, 2) void gemm_mma_kernel(
    const float* __restrict__ pixels)
{
    extern __shared__ char smem[];
    const uint32_t sA = smem_u32(smem);
    const uint32_t sB = sA + ASMEM;
    const uint32_t mbB = sA + MBAR_OFF;       // 2 barriers, 8B each
    const int tid = threadIdx.x;
    const int wid = tid >> 5;
    const int lane = tid & 31;
    const int wm = wid >> 1;    // 0..3 (32 M rows)
    const int wn = wid & 1;     // 0..1 (32 N cols)
    const int m0 = blockIdx.x * BM;
    const int grp = blockIdx.y;
    const int t0 = grp * NT_G;               // first global N-tile

    if (tid == 0) {
        MBARRIER_INIT(mbB + 0, 1);
        MBARRIER_INIT(mbB + 8, 1);
        MBARRIER_EXPECT_TX(mbB + 0, BBUF);
        bulk_cp(sB, (const char*)g_bsw + (size_t)t0 * BBUF, BBUF, mbB + 0);
    }

    // ---- build A tile in smem from pixels (fused patchify) ----
    {
        const int m = tid >> 1;
        const int half = tid & 1;
        const int mg = m0 + m;
        const int b = mg >> 6, p = mg & 63;
        const int r = p >> 3, c = p & 7;
        const float* pix = pixels + (size_t)b * 3 * 4096 + c * 8;
#pragma unroll
        for (int gi = 0; gi < 12; gi++) {
            int g = half * 12 + gi;
            int d0 = g * 8;
            int ch = d0 >> 6;
            int pr = (d0 & 63) >> 3;
            const float4* src = (const float4*)(pix + (size_t)ch * 4096 + (r * 8 + pr) * 64);
            float4 v0 = src[0], v1 = src[1];
            __half2 h0 = __floats2half2_rn(v0.x, v0.y);
            __half2 h1 = __floats2half2_rn(v0.z, v0.w);
            __half2 h2 = __floats2half2_rn(v1.x, v1.y);
            __half2 h3 = __floats2half2_rn(v1.z, v1.w);
            uint4 u;
            u.x = *(uint32_t*)&h0; u.y = *(uint32_t*)&h1;
            u.z = *(uint32_t*)&h2; u.w = *(uint32_t*)&h3;
            *(uint4*)(smem + m * AROWB + ((g ^ (m & 7)) * 16)) = u;
        }
    }
    __syncthreads();

    float acc[2][2][2][4];
#pragma unroll
    for (int a = 0; a < 2; a++)
#pragma unroll
        for (int b = 0; b < 2; b++)
#pragma unroll
            for (int c = 0; c < 2; c++)
#pragma unroll
                for (int d = 0; d < 4; d++) acc[a][b][c][d] = 0.0f;

    float b1[4], b2[4];
    int   i1[4];
#pragma unroll
    for (int s = 0; s < 4; s++) { b1[s] = -3.0e38f; b2[s] = -3.0e38f; i1[s] = 0; }

    const int krow_base = (lane & 7) + ((lane & 16) ? 8 : 0);

    for (int j = 0; j < NT_G; ++j) {
        const int slot = j & 1;
        if (j) __syncthreads();
        if (tid == 0 && j + 1 < NT_G) {
            MBARRIER_EXPECT_TX(mbB + (slot ^ 1) * 8, BBUF);
            bulk_cp(sB + (slot ^ 1) * BBUF,
                    (const char*)g_bsw + (size_t)(t0 + j + 1) * BBUF,
                    BBUF, mbB + (slot ^ 1) * 8);
        }
        MBARRIER_WAIT_PARITY(mbB + slot * 8, (j >> 1) & 1);

        const uint32_t bbuf = sB + slot * BBUF;

        uint32_t af[2][2][4], bf[2][2][4];
#pragma unroll
        for (int mm = 0; mm < 2; mm++) {
            int r = wm * 32 + mm * 16 + (lane & 15);
            int g = (lane >> 4);
            ldsm4(af[0][mm], sA + r * AROWB + ((g ^ (r & 7)) * 16));
        }
#pragma unroll
        for (int nn2 = 0; nn2 < 2; nn2++) {
            int krow = krow_base;
            int g = wn * 4 + nn2 * 2 + ((lane >> 3) & 1);
            ldsm4t(bf[0][nn2], bbuf + krow * 128 + ((g ^ (krow & 7)) * 16));
        }

#pragma unroll
        for (int kk = 0; kk < KSTEPS; kk++) {
            const int cur = kk & 1, nxt = cur ^ 1;
            if (kk + 1 < KSTEPS) {
                const int k2 = kk + 1;
#pragma unroll
                for (int mm = 0; mm < 2; mm++) {
                    int r = wm * 32 + mm * 16 + (lane & 15);
                    int g = k2 * 2 + (lane >> 4);
                    ldsm4(af[nxt][mm], sA + r * AROWB + ((g ^ (r & 7)) * 16));
                }
                const int kc2 = k2 >> 2, kl2 = k2 & 3;
#pragma unroll
                for (int nn2 = 0; nn2 < 2; nn2++) {
                    int krow = kl2 * 16 + krow_base;
                    int g = wn * 4 + nn2 * 2 + ((lane >> 3) & 1);
                    ldsm4t(bf[nxt][nn2],
                           bbuf + kc2 * 8192 + krow * 128 + ((g ^ (krow & 7)) * 16));
                }
            }
#pragma unroll
            for (int nn2 = 0; nn2 < 2; nn2++) {
#pragma unroll
                for (int mm = 0; mm < 2; mm++) {
                    mma16816(acc[mm][nn2][0], af[cur][mm], bf[cur][nn2][0], bf[cur][nn2][2]);
                    mma16816(acc[mm][nn2][1], af[cur][mm], bf[cur][nn2][1], bf[cur][nn2][3]);
                }
            }
        }

        // ---- fold into running top-2 (ascending codes within group) ----
        const int colb = (t0 + j) * BN + wn * 32 + 2 * (lane & 3);
#pragma unroll
        for (int s = 0; s < 4; s++) {
            const int mm = s >> 1, h = s & 1;
#pragma unroll
            for (int nn2 = 0; nn2 < 2; nn2++) {
#pragma unroll
                for (int hn = 0; hn < 2; hn++) {
                    int cb = colb + nn2 * 16 + hn * 8;
                    float v0 = acc[mm][nn2][hn][h * 2];
                    if (v0 > b1[s]) { b2[s] = b1[s]; b1[s] = v0; i1[s] = cb; }
                    else if (v0 > b2[s]) b2[s] = v0;
                    float v1 = acc[mm][nn2][hn][h * 2 + 1];
                    if (v1 > b1[s]) { b2[s] = b1[s]; b1[s] = v1; i1[s] = cb + 1; }
                    else if (v1 > b2[s]) b2[s] = v1;
                    acc[mm][nn2][hn][h * 2] = 0.0f;
                    acc[mm][nn2][hn][h * 2 + 1] = 0.0f;
                }
            }
        }
    }

    // ---- quad-lane merge ----
#pragma unroll
    for (int s = 0; s < 4; s++) {
#pragma unroll
        for (int ofs = 1; ofs <= 2; ofs <<= 1) {
            float w1 = __shfl_xor_sync(0xFFFFFFFFu, b1[s], ofs);
            float w2 = __shfl_xor_sync(0xFFFFFFFFu, b2[s], ofs);
            int   k1 = __shfl_xor_sync(0xFFFFFFFFu, i1[s], ofs);
            if (w1 > b1[s] || (w1 == b1[s] && k1 < i1[s])) {
                b2[s] = fmaxf(b1[s], w2); b1[s] = w1; i1[s] = k1;
            } else {
                b2[s] = fmaxf(b2[s], w1);
            }
        }
    }

    // ---- cross-warp reduction via smem, then write group partials ----
    __syncthreads();
    float* rv1 = (float*)(smem + ASMEM);
    float* rv2 = rv1 + BM * 2;
    int*   ri1 = (int*)(rv2 + BM * 2);
    if ((lane & 3) == 0) {
#pragma unroll
        for (int s = 0; s < 4; s++) {
            int row = wm * 32 + (s >> 1) * 16 + (s & 1) * 8 + (lane >> 2);
            rv1[row * 2 + wn] = b1[s];
            rv2[row * 2 + wn] = b2[s];
            ri1[row * 2 + wn] = i1[s];
        }
    }
    __syncthreads();
    if (tid < BM) {
        float v1 = rv1[tid * 2], v2 = rv2[tid * 2];
        int   j1 = ri1[tid * 2];
        float w1 = rv1[tid * 2 + 1], w2 = rv2[tid * 2 + 1];
        int   k1 = ri1[tid * 2 + 1];
        if (w1 > v1 || (w1 == v1 && k1 < j1)) { v2 = fmaxf(v1, w2); v1 = w1; j1 = k1; }
        else v2 = fmaxf(v2, w1);
        size_t o = (size_t)(m0 + tid) * NGROUP + grp;
        g_pv1[o] = v1;
        g_pv2[o] = v2;
        g_pi1[o] = j1;
    }
}

// ===========================================================================
// 2b) Merge group partials (ascending group -> first-occurrence), flag ties.
// ===========================================================================
__global__ void gemm_combine_kernel(float* __restrict__ outI) {
    int row = blockIdx.x * blockDim.x + threadIdx.x;
    size_t o = (size_t)row * NGROUP;
    float v1 = g_pv1[o], v2 = g_pv2[o];
    int   j1 = g_pi1[o];
#pragma unroll
    for (int s = 1; s < NGROUP; s++) {
        float w1 = g_pv1[o + s], w2 = g_pv2[o + s];
        int   k1 = g_pi1[o + s];
        if (w1 > v1 || (w1 == v1 && k1 < j1)) { v2 = fmaxf(v1, w2); v1 = w1; j1 = k1; }
        else v2 = fmaxf(v2, w1);
    }
    g_indices[row] = j1;
    outI[row] = (float)j1;
    if (v1 - v2 < DELTA) {
        int s = atomicAdd(&g_nflag, 1);
        g_flagged[s] = row;
    }
}

// ===========================================================================
// 3a) Tiled batch rescore (reads pixels; unchanged from R11).
// ===========================================================================
__global__ __launch_bounds__(256) void rescore_part_kernel(
    const float* __restrict__ pixels, const float* __restrict__ cb)
{
    __shared__ float4 sp[48][20];
    __shared__ float  rv[16][16];
    __shared__ int    ri[16][16];
    const int nf = g_nflag;
    if (nf == 0) return;
    const int ngroups = (nf + 15) >> 4;
    const int nitems = ngroups * 4;
    const int tid = threadIdx.x;
    const int r = tid & 15;
    const int cl = tid >> 4;
    const float4* pix4 = (const float4*)pixels;

    for (int item = blockIdx.x; item < nitems; item += gridDim.x) {
        const int g = item >> 2;
        const int s = item & 3;
        __syncthreads();
        for (int i = tid; i < 16 * 48; i += 256) {
            int rr = i / 48, qq = i % 48;
            int f = g * 16 + rr;
            int m = g_flagged[(f < nf) ? f : (nf - 1)];
            int b = m >> 6, p = m & 63;
            int pr_ = (p >> 3), pc_ = (p & 7);
            int d0 = qq * 4;
            int ch = d0 >> 6, rem = d0 & 63;
            int prr = rem >> 3, pcc = rem & 7;
            sp[qq][rr] = pix4[((size_t)(b * 3 + ch) * 64 + pr_ * 8 + prr) * 16
                              + pc_ * 2 + (pcc >> 2)];
        }
        __syncthreads();

        float bv = -3.0e38f;
        int bi = 0;
        const int kbase = s * 1024 + cl * 64;
        for (int j = 0; j < 64; j++) {
            const int k = kbase + j;
            const float4* crow = (const float4*)(cb + (size_t)k * PD);
            float acc = 0.0f;
#pragma unroll 12
            for (int q = 0; q < 48; q++) {
                float4 c4 = crow[q];
                float4 p4 = sp[q][r];
                acc = fmaf(p4.x, c4.x, acc);
                acc = fmaf(p4.y, c4.y, acc);
                acc = fmaf(p4.z, c4.z, acc);
                acc = fmaf(p4.w, c4.w, acc);
            }
            if (acc > bv) { bv = acc; bi = k; }
        }
        rv[r][cl] = bv;
        ri[r][cl] = bi;
        __syncthreads();
        if (tid < 16) {
            float v = rv[tid][0];
            int ix = ri[tid][0];
#pragma unroll
            for (int t = 1; t < 16; t++) {
                float w = rv[tid][t];
                int k1 = ri[tid][t];
                if (w > v || (w == v && k1 < ix)) { v = w; ix = k1; }
            }
            int f = g * 16 + tid;
            if (f < nf) {
                g_part_val[(size_t)f * 4 + s] = v;
                g_part_idx[(size_t)f * 4 + s] = ix;
            }
        }
    }
}

__global__ void rescore_combine_kernel(float* __restrict__ outI) {
    int f = blockIdx.x * blockDim.x + threadIdx.x;
    if (f >= g_nflag) return;
    float bv = g_part_val[(size_t)f * 4];
    int bi = g_part_idx[(size_t)f * 4];
#pragma unroll
    for (int s = 1; s < 4; s++) {
        float v = g_part_val[(size_t)f * 4 + s];
        int ix = g_part_idx[(size_t)f * 4 + s];
        if (v > bv || (v == bv && ix < bi)) { bv = v; bi = ix; }
    }
    int m = g_flagged[f];
    g_indices[m] = bi;
    outI[m] = (float)bi;
}

// ===========================================================================
// 4) Fused tail: embed means (y=0,1) + VSA (y=2).
// ===========================================================================
__global__ __launch_bounds__(256) void tail_kernel(
    const float* __restrict__ emb, const float* __restrict__ cbv,
    const float* __restrict__ roles,
    float* __restrict__ outR, float* __restrict__ outL, float* __restrict__ outV)
{
    const int b = blockIdx.x;
    if (blockIdx.y < 2) {
        __shared__ int sIdx[NP];
        if (threadIdx.x < NP) sIdx[threadIdx.x] = g_indices[b * NP + threadIdx.x];
        __syncthreads();
        const int e4 = blockIdx.y * 256 + threadIdx.x;
        const float4* emb4 = (const float4*)emb;
        float4 s = make_float4(0.f, 0.f, 0.f, 0.f);
        float4 sl = make_float4(0.f, 0.f, 0.f, 0.f);
#pragma unroll 8
        for (int p = 0; p < NP; p++) {
            float4 v = emb4[(size_t)sIdx[p] * (ED / 4) + e4];
            s.x += v.x; s.y += v.y; s.z += v.z; s.w += v.w;
            int r = p >> 3, c = p & 7;
            if (r >= 3 && r < 6 && c >= 3 && c < 6) {
                sl.x += v.x; sl.y += v.y; sl.z += v.z; sl.w += v.w;
            }
        }
        const float iR = 1.0f / 64.0f, iL = 1.0f / 9.0f;
        ((float4*)outR)[(size_t)b * (ED / 4) + e4] =
            make_float4(s.x * iR, s.y * iR, s.z * iR, s.w * iR);
        ((float4*)outL)[(size_t)b * (ED / 4) + e4] =
            make_float4(sl.x * iL, sl.y * iL, sl.z * iL, sl.w * iL);
    } else {
        __shared__ int vIdx[16];
        __shared__ int vPos[16];
        if (threadIdx.x < 16) {
            int r = 2 + (threadIdx.x >> 2);
            int c = 2 + (threadIdx.x & 3);
            int p = r * 8 + c;
            vPos[threadIdx.x] = p;
            vIdx[threadIdx.x] = g_indices[b * NP + p];
        }
        __syncthreads();
        const float4* cbv4 = (const float4*)cbv;
        const float4* rol4 = (const float4*)roles;
#pragma unroll
        for (int half = 0; half < 2; half++) {
            const int v4 = half * 256 + threadIdx.x;
            int cx = 0, cy = 0, cz = 0, cw = 0;
#pragma unroll
            for (int t = 0; t < 16; t++) {
                float4 a = cbv4[(size_t)vIdx[t] * (VD / 4) + v4];
                float4 q = rol4[(size_t)vPos[t] * (VD / 4) + v4];
                cx += (a.x != q.x); cy += (a.y != q.y);
                cz += (a.z != q.z); cw += (a.w != q.w);
            }
            ((float4*)outV)[(size_t)b * (VD / 4) + v4] =
                make_float4(cx > 8 ? 1.f : 0.f, cy > 8 ? 1.f : 0.f,
                            cz > 8 ? 1.f : 0.f, cw > 8 ? 1.f : 0.f);
        }
    }
}

// ===========================================================================
extern "C" void kernel_launch(void* const* d_in, const int* in_sizes, int n_in,
                              void* d_out, int out_size)
{
    const float* pixels     = (const float*)d_in[0];
    const float* codebook   = (const float*)d_in[1];
    const float* embeddings = (const float*)d_in[2];
    const float* cbv        = (const float*)d_in[3];
    const float* roles      = (const float*)d_in[4];

    float* out  = (float*)d_out;
    float* outR = out;
    float* outV = out + (size_t)BATCH * ED;
    float* outI = out + 2 * (size_t)BATCH * ED;
    float* outL = out + 2 * (size_t)BATCH * ED + (size_t)BATCH * NP;

    static bool attr_set = false;
    if (!attr_set) {
        cudaFuncSetAttribute(gemm_mma_kernel,
                             cudaFuncAttributeMaxDynamicSharedMemorySize, GEMM_SMEM);
        attr_set = true;
    }

    prep_kernel<<<CB_BLOCKS + 1, 256>>>(codebook);
    gemm_mma_kernel<<<dim3(MROWS / BM, NGROUP), GEMM_THREADS, GEMM_SMEM>>>(pixels);
    gemm_combine_kernel<<<MROWS / 256, 256>>>(outI);
    rescore_part_kernel<<<1024, 256>>>(pixels, codebook);
    rescore_combine_kernel<<<MROWS / 256, 256>>>(outI);
    tail_kernel<<<dim3(BATCH, 3), 256>>>(embeddings, cbv, roles, outR, outL, outV);
}

// round 13
// speedup vs baseline: 1.3601x; 1.3601x over previous
#include <cuda_runtime.h>
#include <cuda_fp16.h>
#include <cstdint>

// ===========================================================================
// VQPatchEncoder — single-term fp16 mma.sync GEMM + DELTA-certified exact
// argmax. R13: rescore rebuilt — 16 code-slices (vs 4) and 4 interleaved
// sequential fp32 chains per thread (ILP/MLP x4, bit-identical per-code
// dots, ascending-order folds everywhere). GEMM/prep/tail = R12.
// ===========================================================================

#define BATCH 1024
#define NP    64
#define PD    192
#define KC    4096
#define ED    2048
#define VD    2048
#define MROWS (BATCH * NP)      // 65536
#define BM    128
#define BN    64
#define NGROUP 4
#define NT_G   16                // N-tiles per group
#define KSTEPS (PD / 16)         // 12
#define AROWB  (PD * 2)          // 384
#define ASMEM  (BM * AROWB)      // 49152
#define BBUF   (PD * BN * 2)     // 24576 (full-K tile)
#define MBAR_OFF (ASMEM + 2 * BBUF)           // 98304
#define GEMM_SMEM (MBAR_OFF + 32)             // 98336
#define GEMM_THREADS 256
#define DELTA 4e-3f
#define NSLICE 16                 // rescore code slices (256 codes each)

// ---- device-global scratch ------------------------------------------------
__device__ __align__(16) __half g_bsw[(size_t)PD * KC];   // per-tile smem images
__device__ int    g_indices[MROWS];
__device__ int    g_flagged[MROWS];
__device__ int    g_nflag;
__device__ float  g_pv1[(size_t)MROWS * NGROUP];   // GEMM group partials
__device__ float  g_pv2[(size_t)MROWS * NGROUP];
__device__ int    g_pi1[(size_t)MROWS * NGROUP];
__device__ float  g_part_val[(size_t)MROWS * NSLICE];  // rescore partials
__device__ int    g_part_idx[(size_t)MROWS * NSLICE];

__device__ __forceinline__ uint32_t smem_u32(const void* p) {
    uint32_t a;
    asm("{ .reg .u64 t; cvta.to.shared.u64 t, %1; cvt.u32.u64 %0, t; }"
        : "=r"(a) : "l"(p));
    return a;
}

#define MBARRIER_INIT(mbar, cnt) \
    asm volatile("mbarrier.init.shared.b64 [%0], %1;" \
                 :: "r"((uint32_t)(mbar)), "r"((uint32_t)(cnt)) : "memory")
#define MBARRIER_EXPECT_TX(mbar, bytes) \
    asm volatile("mbarrier.arrive.expect_tx.shared.b64 _, [%0], %1;" \
                 :: "r"((uint32_t)(mbar)), "r"((uint32_t)(bytes)) : "memory")

#define MBARRIER_WAIT_PARITY(mbar_addr, phase_parity) do {                        \
    uint32_t _mbar = (uint32_t)(mbar_addr);                                       \
    uint32_t _par  = (uint32_t)(phase_parity);                                    \
    uint32_t _done;                                                               \
    asm volatile("{\n\t.reg .pred p;\n\t"                                         \
        "mbarrier.try_wait.parity.acquire.cta.shared::cta.b64 p, [%1], %2;\n\t"   \
        "selp.b32 %0, 1, 0, p;\n\t}"                                              \
        : "=r"(_done) : "r"(_mbar), "r"(_par) : "memory");                        \
    if (!_done) {                                                                 \
        asm volatile("{\n\t.reg .pred P1;\n\t"                                    \
            "WAIT_LOOP_%=:\n\t"                                                   \
            "mbarrier.try_wait.parity.acquire.cta.shared::cta.b64 P1, [%0], %1, 0x989680;\n\t" \
            "@P1 bra.uni WAIT_DONE_%=;\n\t"                                       \
            "bra.uni WAIT_LOOP_%=;\n\t"                                           \
            "WAIT_DONE_%=:\n\t}"                                                  \
            :: "r"(_mbar), "r"(_par) : "memory");                                 \
    }                                                                             \
} while (0)

__device__ __forceinline__ void bulk_cp(uint32_t dst, const void* src,
                                        uint32_t bytes, uint32_t mbar) {
    asm volatile(
        "cp.async.bulk.shared::cta.global.mbarrier::complete_tx::bytes "
        "[%0], [%1], %2, [%3];"
        :: "r"(dst), "l"(src), "r"(bytes), "r"(mbar) : "memory");
}

__device__ __forceinline__ void ldsm4(uint32_t* r, uint32_t addr) {
    asm volatile("ldmatrix.sync.aligned.m8n8.x4.shared.b16 {%0,%1,%2,%3}, [%4];"
                 : "=r"(r[0]), "=r"(r[1]), "=r"(r[2]), "=r"(r[3]) : "r"(addr));
}
__device__ __forceinline__ void ldsm4t(uint32_t* r, uint32_t addr) {
    asm volatile("ldmatrix.sync.aligned.m8n8.x4.trans.shared.b16 {%0,%1,%2,%3}, [%4];"
                 : "=r"(r[0]), "=r"(r[1]), "=r"(r[2]), "=r"(r[3]) : "r"(addr));
}
__device__ __forceinline__ void mma16816(float* c, const uint32_t* a,
                                         uint32_t b0, uint32_t b1) {
    asm volatile(
        "mma.sync.aligned.m16n8k16.row.col.f32.f16.f16.f32 "
        "{%0,%1,%2,%3}, {%4,%5,%6,%7}, {%8,%9}, {%0,%1,%2,%3};"
        : "+f"(c[0]), "+f"(c[1]), "+f"(c[2]), "+f"(c[3])
        : "r"(a[0]), "r"(a[1]), "r"(a[2]), "r"(a[3]), "r"(b0), "r"(b1));
}

// ===========================================================================
// 1) Prep: codebook smem-image layout + flag reset only.
// ===========================================================================
#define CB_BLOCKS  ((PD * KC) / 256)             // 3072
__global__ void prep_kernel(const float* __restrict__ cbk) {
    int bid = blockIdx.x;
    if (bid < CB_BLOCKS) {
        int idx = bid * 256 + threadIdx.x;
        int n = idx % KC;
        int d = idx / KC;
        int t = n >> 6, nt = n & 63;
        int kc = d >> 6, r = d & 63;
        int g = nt >> 3;
        size_t half_off = (size_t)(t * 3 + kc) * 4096
                        + r * 64 + ((g ^ (r & 7)) * 8) + (nt & 7);
        g_bsw[half_off] = __float2half_rn(cbk[(size_t)n * PD + d]);
    } else {
        if (threadIdx.x == 0) g_nflag = 0;
    }
}

// ===========================================================================
// 2) fp16 mma.sync GEMM, one (M-tile, N-group) per CTA. Grid (512, 4).
// ===========================================================================
__global__ __launch_bounds__(GEMM_THREADS, 2) void gemm_mma_kernel(
    const float* __restrict__ pixels)
{
    extern __shared__ char smem[];
    const uint32_t sA = smem_u32(smem);
    const uint32_t sB = sA + ASMEM;
    const uint32_t mbB = sA + MBAR_OFF;
    const int tid = threadIdx.x;
    const int wid = tid >> 5;
    const int lane = tid & 31;
    const int wm = wid >> 1;
    const int wn = wid & 1;
    const int m0 = blockIdx.x * BM;
    const int grp = blockIdx.y;
    const int t0 = grp * NT_G;

    if (tid == 0) {
        MBARRIER_INIT(mbB + 0, 1);
        MBARRIER_INIT(mbB + 8, 1);
        MBARRIER_EXPECT_TX(mbB + 0, BBUF);
        bulk_cp(sB, (const char*)g_bsw + (size_t)t0 * BBUF, BBUF, mbB + 0);
    }

    // ---- build A tile in smem from pixels (fused patchify) ----
    {
        const int m = tid >> 1;
        const int half = tid & 1;
        const int mg = m0 + m;
        const int b = mg >> 6, p = mg & 63;
        const int r = p >> 3, c = p & 7;
        const float* pix = pixels + (size_t)b * 3 * 4096 + c * 8;
#pragma unroll
        for (int gi = 0; gi < 12; gi++) {
            int g = half * 12 + gi;
            int d0 = g * 8;
            int ch = d0 >> 6;
            int pr = (d0 & 63) >> 3;
            const float4* src = (const float4*)(pix + (size_t)ch * 4096 + (r * 8 + pr) * 64);
            float4 v0 = src[0], v1 = src[1];
            __half2 h0 = __floats2half2_rn(v0.x, v0.y);
            __half2 h1 = __floats2half2_rn(v0.z, v0.w);
            __half2 h2 = __floats2half2_rn(v1.x, v1.y);
            __half2 h3 = __floats2half2_rn(v1.z, v1.w);
            uint4 u;
            u.x = *(uint32_t*)&h0; u.y = *(uint32_t*)&h1;
            u.z = *(uint32_t*)&h2; u.w = *(uint32_t*)&h3;
            *(uint4*)(smem + m * AROWB + ((g ^ (m & 7)) * 16)) = u;
        }
    }
    __syncthreads();

    float acc[2][2][2][4];
#pragma unroll
    for (int a = 0; a < 2; a++)
#pragma unroll
        for (int b = 0; b < 2; b++)
#pragma unroll
            for (int c = 0; c < 2; c++)
#pragma unroll
                for (int d = 0; d < 4; d++) acc[a][b][c][d] = 0.0f;

    float b1[4], b2[4];
    int   i1[4];
#pragma unroll
    for (int s = 0; s < 4; s++) { b1[s] = -3.0e38f; b2[s] = -3.0e38f; i1[s] = 0; }

    const int krow_base = (lane & 7) + ((lane & 16) ? 8 : 0);

    for (int j = 0; j < NT_G; ++j) {
        const int slot = j & 1;
        if (j) __syncthreads();
        if (tid == 0 && j + 1 < NT_G) {
            MBARRIER_EXPECT_TX(mbB + (slot ^ 1) * 8, BBUF);
            bulk_cp(sB + (slot ^ 1) * BBUF,
                    (const char*)g_bsw + (size_t)(t0 + j + 1) * BBUF,
                    BBUF, mbB + (slot ^ 1) * 8);
        }
        MBARRIER_WAIT_PARITY(mbB + slot * 8, (j >> 1) & 1);

        const uint32_t bbuf = sB + slot * BBUF;

        uint32_t af[2][2][4], bf[2][2][4];
#pragma unroll
        for (int mm = 0; mm < 2; mm++) {
            int r = wm * 32 + mm * 16 + (lane & 15);
            int g = (lane >> 4);
            ldsm4(af[0][mm], sA + r * AROWB + ((g ^ (r & 7)) * 16));
        }
#pragma unroll
        for (int nn2 = 0; nn2 < 2; nn2++) {
            int krow = krow_base;
            int g = wn * 4 + nn2 * 2 + ((lane >> 3) & 1);
            ldsm4t(bf[0][nn2], bbuf + krow * 128 + ((g ^ (krow & 7)) * 16));
        }

#pragma unroll
        for (int kk = 0; kk < KSTEPS; kk++) {
            const int cur = kk & 1, nxt = cur ^ 1;
            if (kk + 1 < KSTEPS) {
                const int k2 = kk + 1;
#pragma unroll
                for (int mm = 0; mm < 2; mm++) {
                    int r = wm * 32 + mm * 16 + (lane & 15);
                    int g = k2 * 2 + (lane >> 4);
                    ldsm4(af[nxt][mm], sA + r * AROWB + ((g ^ (r & 7)) * 16));
                }
                const int kc2 = k2 >> 2, kl2 = k2 & 3;
#pragma unroll
                for (int nn2 = 0; nn2 < 2; nn2++) {
                    int krow = kl2 * 16 + krow_base;
                    int g = wn * 4 + nn2 * 2 + ((lane >> 3) & 1);
                    ldsm4t(bf[nxt][nn2],
                           bbuf + kc2 * 8192 + krow * 128 + ((g ^ (krow & 7)) * 16));
                }
            }
#pragma unroll
            for (int nn2 = 0; nn2 < 2; nn2++) {
#pragma unroll
                for (int mm = 0; mm < 2; mm++) {
                    mma16816(acc[mm][nn2][0], af[cur][mm], bf[cur][nn2][0], bf[cur][nn2][2]);
                    mma16816(acc[mm][nn2][1], af[cur][mm], bf[cur][nn2][1], bf[cur][nn2][3]);
                }
            }
        }

        const int colb = (t0 + j) * BN + wn * 32 + 2 * (lane & 3);
#pragma unroll
        for (int s = 0; s < 4; s++) {
            const int mm = s >> 1, h = s & 1;
#pragma unroll
            for (int nn2 = 0; nn2 < 2; nn2++) {
#pragma unroll
                for (int hn = 0; hn < 2; hn++) {
                    int cb = colb + nn2 * 16 + hn * 8;
                    float v0 = acc[mm][nn2][hn][h * 2];
                    if (v0 > b1[s]) { b2[s] = b1[s]; b1[s] = v0; i1[s] = cb; }
                    else if (v0 > b2[s]) b2[s] = v0;
                    float v1 = acc[mm][nn2][hn][h * 2 + 1];
                    if (v1 > b1[s]) { b2[s] = b1[s]; b1[s] = v1; i1[s] = cb + 1; }
                    else if (v1 > b2[s]) b2[s] = v1;
                    acc[mm][nn2][hn][h * 2] = 0.0f;
                    acc[mm][nn2][hn][h * 2 + 1] = 0.0f;
                }
            }
        }
    }

#pragma unroll
    for (int s = 0; s < 4; s++) {
#pragma unroll
        for (int ofs = 1; ofs <= 2; ofs <<= 1) {
            float w1 = __shfl_xor_sync(0xFFFFFFFFu, b1[s], ofs);
            float w2 = __shfl_xor_sync(0xFFFFFFFFu, b2[s], ofs);
            int   k1 = __shfl_xor_sync(0xFFFFFFFFu, i1[s], ofs);
            if (w1 > b1[s] || (w1 == b1[s] && k1 < i1[s])) {
                b2[s] = fmaxf(b1[s], w2); b1[s] = w1; i1[s] = k1;
            } else {
                b2[s] = fmaxf(b2[s], w1);
            }
        }
    }

    __syncthreads();
    float* rv1 = (float*)(smem + ASMEM);
    float* rv2 = rv1 + BM * 2;
    int*   ri1 = (int*)(rv2 + BM * 2);
    if ((lane & 3) == 0) {
#pragma unroll
        for (int s = 0; s < 4; s++) {
            int row = wm * 32 + (s >> 1) * 16 + (s & 1) * 8 + (lane >> 2);
            rv1[row * 2 + wn] = b1[s];
            rv2[row * 2 + wn] = b2[s];
            ri1[row * 2 + wn] = i1[s];
        }
    }
    __syncthreads();
    if (tid < BM) {
        float v1 = rv1[tid * 2], v2 = rv2[tid * 2];
        int   j1 = ri1[tid * 2];
        float w1 = rv1[tid * 2 + 1], w2 = rv2[tid * 2 + 1];
        int   k1 = ri1[tid * 2 + 1];
        if (w1 > v1 || (w1 == v1 && k1 < j1)) { v2 = fmaxf(v1, w2); v1 = w1; j1 = k1; }
        else v2 = fmaxf(v2, w1);
        size_t o = (size_t)(m0 + tid) * NGROUP + grp;
        g_pv1[o] = v1;
        g_pv2[o] = v2;
        g_pi1[o] = j1;
    }
}

// ===========================================================================
// 2b) Merge group partials (ascending group -> first-occurrence), flag ties.
// ===========================================================================
__global__ void gemm_combine_kernel(float* __restrict__ outI) {
    int row = blockIdx.x * blockDim.x + threadIdx.x;
    size_t o = (size_t)row * NGROUP;
    float v1 = g_pv1[o], v2 = g_pv2[o];
    int   j1 = g_pi1[o];
#pragma unroll
    for (int s = 1; s < NGROUP; s++) {
        float w1 = g_pv1[o + s], w2 = g_pv2[o + s];
        int   k1 = g_pi1[o + s];
        if (w1 > v1 || (w1 == v1 && k1 < j1)) { v2 = fmaxf(v1, w2); v1 = w1; j1 = k1; }
        else v2 = fmaxf(v2, w1);
    }
    g_indices[row] = j1;
    outI[row] = (float)j1;
    if (v1 - v2 < DELTA) {
        int s = atomicAdd(&g_nflag, 1);
        g_flagged[s] = row;
    }
}

// ===========================================================================
// 3a) Batch rescore v2: 16 code-slices x (16 flagged rows) per item;
//     each thread runs 4 interleaved sequential fp32 chains (codes
//     ascending). Bit-identical per-code dots; first-occurrence tie-break
//     preserved through every fold (thread -> lane -> slice).
// ===========================================================================
__global__ __launch_bounds__(256) void rescore_part_kernel(
    const float* __restrict__ pixels, const float* __restrict__ cb)
{
    __shared__ float4 sp[48][20];
    __shared__ float  rv[16][16];
    __shared__ int    ri[16][16];
    const int nf = g_nflag;
    if (nf == 0) return;
    const int ngroups = (nf + 15) >> 4;
    const int nitems = ngroups * NSLICE;
    const int tid = threadIdx.x;
    const int r = tid & 15;       // row within group
    const int cl = tid >> 4;      // code lane (16 codes each)
    const float4* pix4 = (const float4*)pixels;

    for (int item = blockIdx.x; item < nitems; item += gridDim.x) {
        const int g = item >> 4;
        const int s = item & (NSLICE - 1);
        __syncthreads();
        for (int i = tid; i < 16 * 48; i += 256) {
            int rr = i / 48, qq = i % 48;
            int f = g * 16 + rr;
            int m = g_flagged[(f < nf) ? f : (nf - 1)];
            int b = m >> 6, p = m & 63;
            int pr_ = (p >> 3), pc_ = (p & 7);
            int d0 = qq * 4;
            int ch = d0 >> 6, rem = d0 & 63;
            int prr = rem >> 3, pcc = rem & 7;
            sp[qq][rr] = pix4[((size_t)(b * 3 + ch) * 64 + pr_ * 8 + prr) * 16
                              + pc_ * 2 + (pcc >> 2)];
        }
        __syncthreads();

        float bv = -3.0e38f;
        int bi = 0;
        const int kb = s * 256 + cl * 16;
#pragma unroll
        for (int batch = 0; batch < 4; batch++) {
            const int k0 = kb + batch * 4;
            const float4* c0 = (const float4*)(cb + (size_t)(k0 + 0) * PD);
            const float4* c1 = (const float4*)(cb + (size_t)(k0 + 1) * PD);
            const float4* c2 = (const float4*)(cb + (size_t)(k0 + 2) * PD);
            const float4* c3 = (const float4*)(cb + (size_t)(k0 + 3) * PD);
            float a0 = 0.0f, a1 = 0.0f, a2 = 0.0f, a3 = 0.0f;
#pragma unroll 4
            for (int q = 0; q < 48; q++) {
                float4 p4 = sp[q][r];
                float4 x0 = c0[q];
                a0 = fmaf(p4.x, x0.x, a0); a0 = fmaf(p4.y, x0.y, a0);
                a0 = fmaf(p4.z, x0.z, a0); a0 = fmaf(p4.w, x0.w, a0);
                float4 x1 = c1[q];
                a1 = fmaf(p4.x, x1.x, a1); a1 = fmaf(p4.y, x1.y, a1);
                a1 = fmaf(p4.z, x1.z, a1); a1 = fmaf(p4.w, x1.w, a1);
                float4 x2 = c2[q];
                a2 = fmaf(p4.x, x2.x, a2); a2 = fmaf(p4.y, x2.y, a2);
                a2 = fmaf(p4.z, x2.z, a2); a2 = fmaf(p4.w, x2.w, a2);
                float4 x3 = c3[q];
                a3 = fmaf(p4.x, x3.x, a3); a3 = fmaf(p4.y, x3.y, a3);
                a3 = fmaf(p4.z, x3.z, a3); a3 = fmaf(p4.w, x3.w, a3);
            }
            // ascending code order -> strict '>' keeps first occurrence
            if (a0 > bv) { bv = a0; bi = k0; }
            if (a1 > bv) { bv = a1; bi = k0 + 1; }
            if (a2 > bv) { bv = a2; bi = k0 + 2; }
            if (a3 > bv) { bv = a3; bi = k0 + 3; }
        }
        rv[r][cl] = bv;
        ri[r][cl] = bi;
        __syncthreads();
        if (tid < 16) {
            float v = rv[tid][0];
            int ix = ri[tid][0];
#pragma unroll
            for (int t = 1; t < 16; t++) {
                float w = rv[tid][t];
                int k1 = ri[tid][t];
                if (w > v || (w == v && k1 < ix)) { v = w; ix = k1; }
            }
            int f = g * 16 + tid;
            if (f < nf) {
                g_part_val[(size_t)f * NSLICE + s] = v;
                g_part_idx[(size_t)f * NSLICE + s] = ix;
            }
        }
    }
}

// 3b) Combine slices (ascending s -> lowest-index tiebreak globally).
__global__ void rescore_combine_kernel(float* __restrict__ outI) {
    int f = blockIdx.x * blockDim.x + threadIdx.x;
    if (f >= g_nflag) return;
    float bv = g_part_val[(size_t)f * NSLICE];
    int bi = g_part_idx[(size_t)f * NSLICE];
#pragma unroll
    for (int s = 1; s < NSLICE; s++) {
        float v = g_part_val[(size_t)f * NSLICE + s];
        int ix = g_part_idx[(size_t)f * NSLICE + s];
        if (v > bv || (v == bv && ix < bi)) { bv = v; bi = ix; }
    }
    int m = g_flagged[f];
    g_indices[m] = bi;
    outI[m] = (float)bi;
}

// ===========================================================================
// 4) Fused tail: embed means (y=0,1) + VSA (y=2).
// ===========================================================================
__global__ __launch_bounds__(256) void tail_kernel(
    const float* __restrict__ emb, const float* __restrict__ cbv,
    const float* __restrict__ roles,
    float* __restrict__ outR, float* __restrict__ outL, float* __restrict__ outV)
{
    const int b = blockIdx.x;
    if (blockIdx.y < 2) {
        __shared__ int sIdx[NP];
        if (threadIdx.x < NP) sIdx[threadIdx.x] = g_indices[b * NP + threadIdx.x];
        __syncthreads();
        const int e4 = blockIdx.y * 256 + threadIdx.x;
        const float4* emb4 = (const float4*)emb;
        float4 s = make_float4(0.f, 0.f, 0.f, 0.f);
        float4 sl = make_float4(0.f, 0.f, 0.f, 0.f);
#pragma unroll 8
        for (int p = 0; p < NP; p++) {
            float4 v = emb4[(size_t)sIdx[p] * (ED / 4) + e4];
            s.x += v.x; s.y += v.y; s.z += v.z; s.w += v.w;
            int r = p >> 3, c = p & 7;
            if (r >= 3 && r < 6 && c >= 3 && c < 6) {
                sl.x += v.x; sl.y += v.y; sl.z += v.z; sl.w += v.w;
            }
        }
        const float iR = 1.0f / 64.0f, iL = 1.0f / 9.0f;
        ((float4*)outR)[(size_t)b * (ED / 4) + e4] =
            make_float4(s.x * iR, s.y * iR, s.z * iR, s.w * iR);
        ((float4*)outL)[(size_t)b * (ED / 4) + e4] =
            make_float4(sl.x * iL, sl.y * iL, sl.z * iL, sl.w * iL);
    } else {
        __shared__ int vIdx[16];
        __shared__ int vPos[16];
        if (threadIdx.x < 16) {
            int r = 2 + (threadIdx.x >> 2);
            int c = 2 + (threadIdx.x & 3);
            int p = r * 8 + c;
            vPos[threadIdx.x] = p;
            vIdx[threadIdx.x] = g_indices[b * NP + p];
        }
        __syncthreads();
        const float4* cbv4 = (const float4*)cbv;
        const float4* rol4 = (const float4*)roles;
#pragma unroll
        for (int half = 0; half < 2; half++) {
            const int v4 = half * 256 + threadIdx.x;
            int cx = 0, cy = 0, cz = 0, cw = 0;
#pragma unroll
            for (int t = 0; t < 16; t++) {
                float4 a = cbv4[(size_t)vIdx[t] * (VD / 4) + v4];
                float4 q = rol4[(size_t)vPos[t] * (VD / 4) + v4];
                cx += (a.x != q.x); cy += (a.y != q.y);
                cz += (a.z != q.z); cw += (a.w != q.w);
            }
            ((float4*)outV)[(size_t)b * (VD / 4) + v4] =
                make_float4(cx > 8 ? 1.f : 0.f, cy > 8 ? 1.f : 0.f,
                            cz > 8 ? 1.f : 0.f, cw > 8 ? 1.f : 0.f);
        }
    }
}

// ===========================================================================
extern "C" void kernel_launch(void* const* d_in, const int* in_sizes, int n_in,
                              void* d_out, int out_size)
{
    const float* pixels     = (const float*)d_in[0];
    const float* codebook   = (const float*)d_in[1];
    const float* embeddings = (const float*)d_in[2];
    const float* cbv        = (const float*)d_in[3];
    const float* roles      = (const float*)d_in[4];

    float* out  = (float*)d_out;
    float* outR = out;
    float* outV = out + (size_t)BATCH * ED;
    float* outI = out + 2 * (size_t)BATCH * ED;
    float* outL = out + 2 * (size_t)BATCH * ED + (size_t)BATCH * NP;

    static bool attr_set = false;
    if (!attr_set) {
        cudaFuncSetAttribute(gemm_mma_kernel,
                             cudaFuncAttributeMaxDynamicSharedMemorySize, GEMM_SMEM);
        attr_set = true;
    }

    prep_kernel<<<CB_BLOCKS + 1, 256>>>(codebook);
    gemm_mma_kernel<<<dim3(MROWS / BM, NGROUP), GEMM_THREADS, GEMM_SMEM>>>(pixels);
    gemm_combine_kernel<<<MROWS / 256, 256>>>(outI);
    rescore_part_kernel<<<2048, 256>>>(pixels, codebook);
    rescore_combine_kernel<<<MROWS / 256, 256>>>(outI);
    tail_kernel<<<dim3(BATCH, 3), 256>>>(embeddings, cbv, roles, outR, outL, outV);
}

// round 15
// speedup vs baseline: 1.3841x; 1.0177x over previous
#include <cuda_runtime.h>
#include <cuda_fp16.h>
#include <cstdint>

// ===========================================================================
// VQPatchEncoder — single-term fp16 mma.sync GEMM + DELTA-certified exact
// argmax. R15 = R14 resubmitted (infra failure last round, kernel never ran):
// monolithic GEMM (R11 epilogue) + R13's 16-slice / 4-chain rescore.
// ===========================================================================

#define BATCH 1024
#define NP    64
#define PD    192
#define KC    4096
#define ED    2048
#define VD    2048
#define MROWS (BATCH * NP)      // 65536
#define BM    128
#define BN    64
#define NTILE  (KC / BN)         // 64
#define KSTEPS (PD / 16)         // 12
#define AROWB  (PD * 2)          // 384
#define ASMEM  (BM * AROWB)      // 49152
#define BBUF   (PD * BN * 2)     // 24576 (full-K tile)
#define MBAR_OFF (ASMEM + 2 * BBUF)           // 98304
#define GEMM_SMEM (MBAR_OFF + 32)             // 98336
#define GEMM_THREADS 256
#define DELTA 4e-3f
#define NSLICE 16                 // rescore code slices (256 codes each)

// ---- device-global scratch ------------------------------------------------
__device__ __align__(16) __half g_bsw[(size_t)PD * KC];   // per-tile smem images
__device__ int    g_indices[MROWS];
__device__ int    g_flagged[MROWS];
__device__ int    g_nflag;
__device__ float  g_part_val[(size_t)MROWS * NSLICE];  // rescore partials
__device__ int    g_part_idx[(size_t)MROWS * NSLICE];

__device__ __forceinline__ uint32_t smem_u32(const void* p) {
    uint32_t a;
    asm("{ .reg .u64 t; cvta.to.shared.u64 t, %1; cvt.u32.u64 %0, t; }"
        : "=r"(a) : "l"(p));
    return a;
}

#define MBARRIER_INIT(mbar, cnt) \
    asm volatile("mbarrier.init.shared.b64 [%0], %1;" \
                 :: "r"((uint32_t)(mbar)), "r"((uint32_t)(cnt)) : "memory")
#define MBARRIER_EXPECT_TX(mbar, bytes) \
    asm volatile("mbarrier.arrive.expect_tx.shared.b64 _, [%0], %1;" \
                 :: "r"((uint32_t)(mbar)), "r"((uint32_t)(bytes)) : "memory")

#define MBARRIER_WAIT_PARITY(mbar_addr, phase_parity) do {                        \
    uint32_t _mbar = (uint32_t)(mbar_addr);                                       \
    uint32_t _par  = (uint32_t)(phase_parity);                                    \
    uint32_t _done;                                                               \
    asm volatile("{\n\t.reg .pred p;\n\t"                                         \
        "mbarrier.try_wait.parity.acquire.cta.shared::cta.b64 p, [%1], %2;\n\t"   \
        "selp.b32 %0, 1, 0, p;\n\t}"                                              \
        : "=r"(_done) : "r"(_mbar), "r"(_par) : "memory");                        \
    if (!_done) {                                                                 \
        asm volatile("{\n\t.reg .pred P1;\n\t"                                    \
            "WAIT_LOOP_%=:\n\t"                                                   \
            "mbarrier.try_wait.parity.acquire.cta.shared::cta.b64 P1, [%0], %1, 0x989680;\n\t" \
            "@P1 bra.uni WAIT_DONE_%=;\n\t"                                       \
            "bra.uni WAIT_LOOP_%=;\n\t"                                           \
            "WAIT_DONE_%=:\n\t}"                                                  \
            :: "r"(_mbar), "r"(_par) : "memory");                                 \
    }                                                                             \
} while (0)

__device__ __forceinline__ void bulk_cp(uint32_t dst, const void* src,
                                        uint32_t bytes, uint32_t mbar) {
    asm volatile(
        "cp.async.bulk.shared::cta.global.mbarrier::complete_tx::bytes "
        "[%0], [%1], %2, [%3];"
        :: "r"(dst), "l"(src), "r"(bytes), "r"(mbar) : "memory");
}

__device__ __forceinline__ void ldsm4(uint32_t* r, uint32_t addr) {
    asm volatile("ldmatrix.sync.aligned.m8n8.x4.shared.b16 {%0,%1,%2,%3}, [%4];"
                 : "=r"(r[0]), "=r"(r[1]), "=r"(r[2]), "=r"(r[3]) : "r"(addr));
}
__device__ __forceinline__ void ldsm4t(uint32_t* r, uint32_t addr) {
    asm volatile("ldmatrix.sync.aligned.m8n8.x4.trans.shared.b16 {%0,%1,%2,%3}, [%4];"
                 : "=r"(r[0]), "=r"(r[1]), "=r"(r[2]), "=r"(r[3]) : "r"(addr));
}
__device__ __forceinline__ void mma16816(float* c, const uint32_t* a,
                                         uint32_t b0, uint32_t b1) {
    asm volatile(
        "mma.sync.aligned.m16n8k16.row.col.f32.f16.f16.f32 "
        "{%0,%1,%2,%3}, {%4,%5,%6,%7}, {%8,%9}, {%0,%1,%2,%3};"
        : "+f"(c[0]), "+f"(c[1]), "+f"(c[2]), "+f"(c[3])
        : "r"(a[0]), "r"(a[1]), "r"(a[2]), "r"(a[3]), "r"(b0), "r"(b1));
}

// ===========================================================================
// 1) Prep: codebook smem-image layout + flag reset only.
// ===========================================================================
#define CB_BLOCKS  ((PD * KC) / 256)             // 3072
__global__ void prep_kernel(const float* __restrict__ cbk) {
    int bid = blockIdx.x;
    if (bid < CB_BLOCKS) {
        int idx = bid * 256 + threadIdx.x;
        int n = idx % KC;
        int d = idx / KC;
        int t = n >> 6, nt = n & 63;
        int kc = d >> 6, r = d & 63;
        int g = nt >> 3;
        size_t half_off = (size_t)(t * 3 + kc) * 4096
                        + r * 64 + ((g ^ (r & 7)) * 8) + (nt & 7);
        g_bsw[half_off] = __float2half_rn(cbk[(size_t)n * PD + d]);
    } else {
        if (threadIdx.x == 0) g_nflag = 0;
    }
}

// ===========================================================================
// 2) fp16 mma.sync GEMM + fused top-2 argmax (monolithic, R11 epilogue).
// ===========================================================================
__global__ __launch_bounds__(GEMM_THREADS, 2) void gemm_mma_kernel(
    const float* __restrict__ pixels, float* __restrict__ outI)
{
    extern __shared__ char smem[];
    const uint32_t sA = smem_u32(smem);
    const uint32_t sB = sA + ASMEM;
    const uint32_t mbB = sA + MBAR_OFF;
    const int tid = threadIdx.x;
    const int wid = tid >> 5;
    const int lane = tid & 31;
    const int wm = wid >> 1;    // 0..3 (32 M rows)
    const int wn = wid & 1;     // 0..1 (32 N cols)
    const int m0 = blockIdx.x * BM;

    if (tid == 0) {
        MBARRIER_INIT(mbB + 0, 1);
        MBARRIER_INIT(mbB + 8, 1);
        MBARRIER_EXPECT_TX(mbB + 0, BBUF);
        bulk_cp(sB, (const char*)g_bsw, BBUF, mbB + 0);
    }

    // ---- build A tile in smem from pixels (fused patchify) ----
    {
        const int m = tid >> 1;
        const int half = tid & 1;
        const int mg = m0 + m;
        const int b = mg >> 6, p = mg & 63;
        const int r = p >> 3, c = p & 7;
        const float* pix = pixels + (size_t)b * 3 * 4096 + c * 8;
#pragma unroll
        for (int gi = 0; gi < 12; gi++) {
            int g = half * 12 + gi;
            int d0 = g * 8;
            int ch = d0 >> 6;
            int pr = (d0 & 63) >> 3;
            const float4* src = (const float4*)(pix + (size_t)ch * 4096 + (r * 8 + pr) * 64);
            float4 v0 = src[0], v1 = src[1];
            __half2 h0 = __floats2half2_rn(v0.x, v0.y);
            __half2 h1 = __floats2half2_rn(v0.z, v0.w);
            __half2 h2 = __floats2half2_rn(v1.x, v1.y);
            __half2 h3 = __floats2half2_rn(v1.z, v1.w);
            uint4 u;
            u.x = *(uint32_t*)&h0; u.y = *(uint32_t*)&h1;
            u.z = *(uint32_t*)&h2; u.w = *(uint32_t*)&h3;
            *(uint4*)(smem + m * AROWB + ((g ^ (m & 7)) * 16)) = u;
        }
    }
    __syncthreads();

    float acc[2][2][2][4];
#pragma unroll
    for (int a = 0; a < 2; a++)
#pragma unroll
        for (int b = 0; b < 2; b++)
#pragma unroll
            for (int c = 0; c < 2; c++)
#pragma unroll
                for (int d = 0; d < 4; d++) acc[a][b][c][d] = 0.0f;

    float b1[4], b2[4];
    int   i1[4];
#pragma unroll
    for (int s = 0; s < 4; s++) { b1[s] = -3.0e38f; b2[s] = -3.0e38f; i1[s] = 0; }

    const int krow_base = (lane & 7) + ((lane & 16) ? 8 : 0);

    for (int it = 0; it < NTILE; ++it) {
        const int slot = it & 1;
        if (it) __syncthreads();
        if (tid == 0 && it + 1 < NTILE) {
            MBARRIER_EXPECT_TX(mbB + (slot ^ 1) * 8, BBUF);
            bulk_cp(sB + (slot ^ 1) * BBUF,
                    (const char*)g_bsw + (size_t)(it + 1) * BBUF,
                    BBUF, mbB + (slot ^ 1) * 8);
        }
        MBARRIER_WAIT_PARITY(mbB + slot * 8, (it >> 1) & 1);

        const uint32_t bbuf = sB + slot * BBUF;

        uint32_t af[2][2][4], bf[2][2][4];
#pragma unroll
        for (int mm = 0; mm < 2; mm++) {
            int r = wm * 32 + mm * 16 + (lane & 15);
            int g = (lane >> 4);
            ldsm4(af[0][mm], sA + r * AROWB + ((g ^ (r & 7)) * 16));
        }
#pragma unroll
        for (int nn2 = 0; nn2 < 2; nn2++) {
            int krow = krow_base;
            int g = wn * 4 + nn2 * 2 + ((lane >> 3) & 1);
            ldsm4t(bf[0][nn2], bbuf + krow * 128 + ((g ^ (krow & 7)) * 16));
        }

#pragma unroll
        for (int kk = 0; kk < KSTEPS; kk++) {
            const int cur = kk & 1, nxt = cur ^ 1;
            if (kk + 1 < KSTEPS) {
                const int k2 = kk + 1;
#pragma unroll
                for (int mm = 0; mm < 2; mm++) {
                    int r = wm * 32 + mm * 16 + (lane & 15);
                    int g = k2 * 2 + (lane >> 4);
                    ldsm4(af[nxt][mm], sA + r * AROWB + ((g ^ (r & 7)) * 16));
                }
                const int kc2 = k2 >> 2, kl2 = k2 & 3;
#pragma unroll
                for (int nn2 = 0; nn2 < 2; nn2++) {
                    int krow = kl2 * 16 + krow_base;
                    int g = wn * 4 + nn2 * 2 + ((lane >> 3) & 1);
                    ldsm4t(bf[nxt][nn2],
                           bbuf + kc2 * 8192 + krow * 128 + ((g ^ (krow & 7)) * 16));
                }
            }
#pragma unroll
            for (int nn2 = 0; nn2 < 2; nn2++) {
#pragma unroll
                for (int mm = 0; mm < 2; mm++) {
                    mma16816(acc[mm][nn2][0], af[cur][mm], bf[cur][nn2][0], bf[cur][nn2][2]);
                    mma16816(acc[mm][nn2][1], af[cur][mm], bf[cur][nn2][1], bf[cur][nn2][3]);
                }
            }
        }

        // ---- fold into running top-2 (ascending codes) ----
        const int colb = it * BN + wn * 32 + 2 * (lane & 3);
#pragma unroll
        for (int s = 0; s < 4; s++) {
            const int mm = s >> 1, h = s & 1;
#pragma unroll
            for (int nn2 = 0; nn2 < 2; nn2++) {
#pragma unroll
                for (int hn = 0; hn < 2; hn++) {
                    int cb = colb + nn2 * 16 + hn * 8;
                    float v0 = acc[mm][nn2][hn][h * 2];
                    if (v0 > b1[s]) { b2[s] = b1[s]; b1[s] = v0; i1[s] = cb; }
                    else if (v0 > b2[s]) b2[s] = v0;
                    float v1 = acc[mm][nn2][hn][h * 2 + 1];
                    if (v1 > b1[s]) { b2[s] = b1[s]; b1[s] = v1; i1[s] = cb + 1; }
                    else if (v1 > b2[s]) b2[s] = v1;
                    acc[mm][nn2][hn][h * 2] = 0.0f;
                    acc[mm][nn2][hn][h * 2 + 1] = 0.0f;
                }
            }
        }
    }

    // ---- quad-lane merge ----
#pragma unroll
    for (int s = 0; s < 4; s++) {
#pragma unroll
        for (int ofs = 1; ofs <= 2; ofs <<= 1) {
            float w1 = __shfl_xor_sync(0xFFFFFFFFu, b1[s], ofs);
            float w2 = __shfl_xor_sync(0xFFFFFFFFu, b2[s], ofs);
            int   k1 = __shfl_xor_sync(0xFFFFFFFFu, i1[s], ofs);
            if (w1 > b1[s] || (w1 == b1[s] && k1 < i1[s])) {
                b2[s] = fmaxf(b1[s], w2); b1[s] = w1; i1[s] = k1;
            } else {
                b2[s] = fmaxf(b2[s], w1);
            }
        }
    }

    // ---- cross-warp reduction via smem (reuse B buffers) ----
    __syncthreads();
    float* rv1 = (float*)(smem + ASMEM);
    float* rv2 = rv1 + BM * 2;
    int*   ri1 = (int*)(rv2 + BM * 2);
    if ((lane & 3) == 0) {
#pragma unroll
        for (int s = 0; s < 4; s++) {
            int row = wm * 32 + (s >> 1) * 16 + (s & 1) * 8 + (lane >> 2);
            rv1[row * 2 + wn] = b1[s];
            rv2[row * 2 + wn] = b2[s];
            ri1[row * 2 + wn] = i1[s];
        }
    }
    __syncthreads();
    if (tid < BM) {
        float v1 = rv1[tid * 2], v2 = rv2[tid * 2];
        int   j1 = ri1[tid * 2];
        float w1 = rv1[tid * 2 + 1], w2 = rv2[tid * 2 + 1];
        int   k1 = ri1[tid * 2 + 1];
        if (w1 > v1 || (w1 == v1 && k1 < j1)) { v2 = fmaxf(v1, w2); v1 = w1; j1 = k1; }
        else v2 = fmaxf(v2, w1);
        int row = m0 + tid;
        g_indices[row] = j1;
        outI[row] = (float)j1;
        if (v1 - v2 < DELTA) {
            int s = atomicAdd(&g_nflag, 1);
            g_flagged[s] = row;
        }
    }
}

// ===========================================================================
// 3a) Batch rescore (R13): 16 code-slices x 16 flagged rows per item;
//     4 interleaved sequential fp32 chains per thread, ascending-order folds.
// ===========================================================================
__global__ __launch_bounds__(256) void rescore_part_kernel(
    const float* __restrict__ pixels, const float* __restrict__ cb)
{
    __shared__ float4 sp[48][20];
    __shared__ float  rv[16][16];
    __shared__ int    ri[16][16];
    const int nf = g_nflag;
    if (nf == 0) return;
    const int ngroups = (nf + 15) >> 4;
    const int nitems = ngroups * NSLICE;
    const int tid = threadIdx.x;
    const int r = tid & 15;
    const int cl = tid >> 4;
    const float4* pix4 = (const float4*)pixels;

    for (int item = blockIdx.x; item < nitems; item += gridDim.x) {
        const int g = item >> 4;
        const int s = item & (NSLICE - 1);
        __syncthreads();
        for (int i = tid; i < 16 * 48; i += 256) {
            int rr = i / 48, qq = i % 48;
            int f = g * 16 + rr;
            int m = g_flagged[(f < nf) ? f : (nf - 1)];
            int b = m >> 6, p = m & 63;
            int pr_ = (p >> 3), pc_ = (p & 7);
            int d0 = qq * 4;
            int ch = d0 >> 6, rem = d0 & 63;
            int prr = rem >> 3, pcc = rem & 7;
            sp[qq][rr] = pix4[((size_t)(b * 3 + ch) * 64 + pr_ * 8 + prr) * 16
                              + pc_ * 2 + (pcc >> 2)];
        }
        __syncthreads();

        float bv = -3.0e38f;
        int bi = 0;
        const int kb = s * 256 + cl * 16;
#pragma unroll
        for (int batch = 0; batch < 4; batch++) {
            const int k0 = kb + batch * 4;
            const float4* c0 = (const float4*)(cb + (size_t)(k0 + 0) * PD);
            const float4* c1 = (const float4*)(cb + (size_t)(k0 + 1) * PD);
            const float4* c2 = (const float4*)(cb + (size_t)(k0 + 2) * PD);
            const float4* c3 = (const float4*)(cb + (size_t)(k0 + 3) * PD);
            float a0 = 0.0f, a1 = 0.0f, a2 = 0.0f, a3 = 0.0f;
#pragma unroll 4
            for (int q = 0; q < 48; q++) {
                float4 p4 = sp[q][r];
                float4 x0 = c0[q];
                a0 = fmaf(p4.x, x0.x, a0); a0 = fmaf(p4.y, x0.y, a0);
                a0 = fmaf(p4.z, x0.z, a0); a0 = fmaf(p4.w, x0.w, a0);
                float4 x1 = c1[q];
                a1 = fmaf(p4.x, x1.x, a1); a1 = fmaf(p4.y, x1.y, a1);
                a1 = fmaf(p4.z, x1.z, a1); a1 = fmaf(p4.w, x1.w, a1);
                float4 x2 = c2[q];
                a2 = fmaf(p4.x, x2.x, a2); a2 = fmaf(p4.y, x2.y, a2);
                a2 = fmaf(p4.z, x2.z, a2); a2 = fmaf(p4.w, x2.w, a2);
                float4 x3 = c3[q];
                a3 = fmaf(p4.x, x3.x, a3); a3 = fmaf(p4.y, x3.y, a3);
                a3 = fmaf(p4.z, x3.z, a3); a3 = fmaf(p4.w, x3.w, a3);
            }
            if (a0 > bv) { bv = a0; bi = k0; }
            if (a1 > bv) { bv = a1; bi = k0 + 1; }
            if (a2 > bv) { bv = a2; bi = k0 + 2; }
            if (a3 > bv) { bv = a3; bi = k0 + 3; }
        }
        rv[r][cl] = bv;
        ri[r][cl] = bi;
        __syncthreads();
        if (tid < 16) {
            float v = rv[tid][0];
            int ix = ri[tid][0];
#pragma unroll
            for (int t = 1; t < 16; t++) {
                float w = rv[tid][t];
                int k1 = ri[tid][t];
                if (w > v || (w == v && k1 < ix)) { v = w; ix = k1; }
            }
            int f = g * 16 + tid;
            if (f < nf) {
                g_part_val[(size_t)f * NSLICE + s] = v;
                g_part_idx[(size_t)f * NSLICE + s] = ix;
            }
        }
    }
}

// 3b) Combine slices (ascending s -> lowest-index tiebreak globally).
__global__ void rescore_combine_kernel(float* __restrict__ outI) {
    int f = blockIdx.x * blockDim.x + threadIdx.x;
    if (f >= g_nflag) return;
    float bv = g_part_val[(size_t)f * NSLICE];
    int bi = g_part_idx[(size_t)f * NSLICE];
#pragma unroll
    for (int s = 1; s < NSLICE; s++) {
        float v = g_part_val[(size_t)f * NSLICE + s];
        int ix = g_part_idx[(size_t)f * NSLICE + s];
        if (v > bv || (v == bv && ix < bi)) { bv = v; bi = ix; }
    }
    int m = g_flagged[f];
    g_indices[m] = bi;
    outI[m] = (float)bi;
}

// ===========================================================================
// 4) Fused tail: embed means (y=0,1) + VSA (y=2).
// ===========================================================================
__global__ __launch_bounds__(256) void tail_kernel(
    const float* __restrict__ emb, const float* __restrict__ cbv,
    const float* __restrict__ roles,
    float* __restrict__ outR, float* __restrict__ outL, float* __restrict__ outV)
{
    const int b = blockIdx.x;
    if (blockIdx.y < 2) {
        __shared__ int sIdx[NP];
        if (threadIdx.x < NP) sIdx[threadIdx.x] = g_indices[b * NP + threadIdx.x];
        __syncthreads();
        const int e4 = blockIdx.y * 256 + threadIdx.x;
        const float4* emb4 = (const float4*)emb;
        float4 s = make_float4(0.f, 0.f, 0.f, 0.f);
        float4 sl = make_float4(0.f, 0.f, 0.f, 0.f);
#pragma unroll 8
        for (int p = 0; p < NP; p++) {
            float4 v = emb4[(size_t)sIdx[p] * (ED / 4) + e4];
            s.x += v.x; s.y += v.y; s.z += v.z; s.w += v.w;
            int r = p >> 3, c = p & 7;
            if (r >= 3 && r < 6 && c >= 3 && c < 6) {
                sl.x += v.x; sl.y += v.y; sl.z += v.z; sl.w += v.w;
            }
        }
        const float iR = 1.0f / 64.0f, iL = 1.0f / 9.0f;
        ((float4*)outR)[(size_t)b * (ED / 4) + e4] =
            make_float4(s.x * iR, s.y * iR, s.z * iR, s.w * iR);
        ((float4*)outL)[(size_t)b * (ED / 4) + e4] =
            make_float4(sl.x * iL, sl.y * iL, sl.z * iL, sl.w * iL);
    } else {
        __shared__ int vIdx[16];
        __shared__ int vPos[16];
        if (threadIdx.x < 16) {
            int r = 2 + (threadIdx.x >> 2);
            int c = 2 + (threadIdx.x & 3);
            int p = r * 8 + c;
            vPos[threadIdx.x] = p;
            vIdx[threadIdx.x] = g_indices[b * NP + p];
        }
        __syncthreads();
        const float4* cbv4 = (const float4*)cbv;
        const float4* rol4 = (const float4*)roles;
#pragma unroll
        for (int half = 0; half < 2; half++) {
            const int v4 = half * 256 + threadIdx.x;
            int cx = 0, cy = 0, cz = 0, cw = 0;
#pragma unroll
            for (int t = 0; t < 16; t++) {
                float4 a = cbv4[(size_t)vIdx[t] * (VD / 4) + v4];
                float4 q = rol4[(size_t)vPos[t] * (VD / 4) + v4];
                cx += (a.x != q.x); cy += (a.y != q.y);
                cz += (a.z != q.z); cw += (a.w != q.w);
            }
            ((float4*)outV)[(size_t)b * (VD / 4) + v4] =
                make_float4(cx > 8 ? 1.f : 0.f, cy > 8 ? 1.f : 0.f,
                            cz > 8 ? 1.f : 0.f, cw > 8 ? 1.f : 0.f);
        }
    }
}

// ===========================================================================
extern "C" void kernel_launch(void* const* d_in, const int* in_sizes, int n_in,
                              void* d_out, int out_size)
{
    const float* pixels     = (const float*)d_in[0];
    const float* codebook   = (const float*)d_in[1];
    const float* embeddings = (const float*)d_in[2];
    const float* cbv        = (const float*)d_in[3];
    const float* roles      = (const float*)d_in[4];

    float* out  = (float*)d_out;
    float* outR = out;
    float* outV = out + (size_t)BATCH * ED;
    float* outI = out + 2 * (size_t)BATCH * ED;
    float* outL = out + 2 * (size_t)BATCH * ED + (size_t)BATCH * NP;

    static bool attr_set = false;
    if (!attr_set) {
        cudaFuncSetAttribute(gemm_mma_kernel,
                             cudaFuncAttributeMaxDynamicSharedMemorySize, GEMM_SMEM);
        attr_set = true;
    }

    prep_kernel<<<CB_BLOCKS + 1, 256>>>(codebook);
    gemm_mma_kernel<<<MROWS / BM, GEMM_THREADS, GEMM_SMEM>>>(pixels, outI);
    rescore_part_kernel<<<2048, 256>>>(pixels, codebook);
    rescore_combine_kernel<<<MROWS / 256, 256>>>(outI);
    tail_kernel<<<dim3(BATCH, 3), 256>>>(embeddings, cbv, roles, outR, outL, outV);
}

// round 16
// speedup vs baseline: 1.3953x; 1.0081x over previous
#include <cuda_runtime.h>
#include <cuda_fp16.h>
#include <cstdint>

// ===========================================================================
// VQPatchEncoder — single-term fp16 mma.sync GEMM + DELTA-certified exact
// argmax. R16: rescore widened to 8 interleaved fp32 chains per thread
// (2 ascending batches of 8) — fmaf-issue-bound instead of latency-bound.
// GEMM/prep/tail identical to R15 (563us).
// ===========================================================================

#define BATCH 1024
#define NP    64
#define PD    192
#define KC    4096
#define ED    2048
#define VD    2048
#define MROWS (BATCH * NP)      // 65536
#define BM    128
#define BN    64
#define NTILE  (KC / BN)         // 64
#define KSTEPS (PD / 16)         // 12
#define AROWB  (PD * 2)          // 384
#define ASMEM  (BM * AROWB)      // 49152
#define BBUF   (PD * BN * 2)     // 24576 (full-K tile)
#define MBAR_OFF (ASMEM + 2 * BBUF)           // 98304
#define GEMM_SMEM (MBAR_OFF + 32)             // 98336
#define GEMM_THREADS 256
#define DELTA 4e-3f
#define NSLICE 16                 // rescore code slices (256 codes each)

// ---- device-global scratch ------------------------------------------------
__device__ __align__(16) __half g_bsw[(size_t)PD * KC];   // per-tile smem images
__device__ int    g_indices[MROWS];
__device__ int    g_flagged[MROWS];
__device__ int    g_nflag;
__device__ float  g_part_val[(size_t)MROWS * NSLICE];  // rescore partials
__device__ int    g_part_idx[(size_t)MROWS * NSLICE];

__device__ __forceinline__ uint32_t smem_u32(const void* p) {
    uint32_t a;
    asm("{ .reg .u64 t; cvta.to.shared.u64 t, %1; cvt.u32.u64 %0, t; }"
        : "=r"(a) : "l"(p));
    return a;
}

#define MBARRIER_INIT(mbar, cnt) \
    asm volatile("mbarrier.init.shared.b64 [%0], %1;" \
                 :: "r"((uint32_t)(mbar)), "r"((uint32_t)(cnt)) : "memory")
#define MBARRIER_EXPECT_TX(mbar, bytes) \
    asm volatile("mbarrier.arrive.expect_tx.shared.b64 _, [%0], %1;" \
                 :: "r"((uint32_t)(mbar)), "r"((uint32_t)(bytes)) : "memory")

#define MBARRIER_WAIT_PARITY(mbar_addr, phase_parity) do {                        \
    uint32_t _mbar = (uint32_t)(mbar_addr);                                       \
    uint32_t _par  = (uint32_t)(phase_parity);                                    \
    uint32_t _done;                                                               \
    asm volatile("{\n\t.reg .pred p;\n\t"                                         \
        "mbarrier.try_wait.parity.acquire.cta.shared::cta.b64 p, [%1], %2;\n\t"   \
        "selp.b32 %0, 1, 0, p;\n\t}"                                              \
        : "=r"(_done) : "r"(_mbar), "r"(_par) : "memory");                        \
    if (!_done) {                                                                 \
        asm volatile("{\n\t.reg .pred P1;\n\t"                                    \
            "WAIT_LOOP_%=:\n\t"                                                   \
            "mbarrier.try_wait.parity.acquire.cta.shared::cta.b64 P1, [%0], %1, 0x989680;\n\t" \
            "@P1 bra.uni WAIT_DONE_%=;\n\t"                                       \
            "bra.uni WAIT_LOOP_%=;\n\t"                                           \
            "WAIT_DONE_%=:\n\t}"                                                  \
            :: "r"(_mbar), "r"(_par) : "memory");                                 \
    }                                                                             \
} while (0)

__device__ __forceinline__ void bulk_cp(uint32_t dst, const void* src,
                                        uint32_t bytes, uint32_t mbar) {
    asm volatile(
        "cp.async.bulk.shared::cta.global.mbarrier::complete_tx::bytes "
        "[%0], [%1], %2, [%3];"
        :: "r"(dst), "l"(src), "r"(bytes), "r"(mbar) : "memory");
}

__device__ __forceinline__ void ldsm4(uint32_t* r, uint32_t addr) {
    asm volatile("ldmatrix.sync.aligned.m8n8.x4.shared.b16 {%0,%1,%2,%3}, [%4];"
                 : "=r"(r[0]), "=r"(r[1]), "=r"(r[2]), "=r"(r[3]) : "r"(addr));
}
__device__ __forceinline__ void ldsm4t(uint32_t* r, uint32_t addr) {
    asm volatile("ldmatrix.sync.aligned.m8n8.x4.trans.shared.b16 {%0,%1,%2,%3}, [%4];"
                 : "=r"(r[0]), "=r"(r[1]), "=r"(r[2]), "=r"(r[3]) : "r"(addr));
}
__device__ __forceinline__ void mma16816(float* c, const uint32_t* a,
                                         uint32_t b0, uint32_t b1) {
    asm volatile(
        "mma.sync.aligned.m16n8k16.row.col.f32.f16.f16.f32 "
        "{%0,%1,%2,%3}, {%4,%5,%6,%7}, {%8,%9}, {%0,%1,%2,%3};"
        : "+f"(c[0]), "+f"(c[1]), "+f"(c[2]), "+f"(c[3])
        : "r"(a[0]), "r"(a[1]), "r"(a[2]), "r"(a[3]), "r"(b0), "r"(b1));
}

// ===========================================================================
// 1) Prep: codebook smem-image layout + flag reset only.
// ===========================================================================
#define CB_BLOCKS  ((PD * KC) / 256)             // 3072
__global__ void prep_kernel(const float* __restrict__ cbk) {
    int bid = blockIdx.x;
    if (bid < CB_BLOCKS) {
        int idx = bid * 256 + threadIdx.x;
        int n = idx % KC;
        int d = idx / KC;
        int t = n >> 6, nt = n & 63;
        int kc = d >> 6, r = d & 63;
        int g = nt >> 3;
        size_t half_off = (size_t)(t * 3 + kc) * 4096
                        + r * 64 + ((g ^ (r & 7)) * 8) + (nt & 7);
        g_bsw[half_off] = __float2half_rn(cbk[(size_t)n * PD + d]);
    } else {
        if (threadIdx.x == 0) g_nflag = 0;
    }
}

// ===========================================================================
// 2) fp16 mma.sync GEMM + fused top-2 argmax (monolithic, unchanged).
// ===========================================================================
__global__ __launch_bounds__(GEMM_THREADS, 2) void gemm_mma_kernel(
    const float* __restrict__ pixels, float* __restrict__ outI)
{
    extern __shared__ char smem[];
    const uint32_t sA = smem_u32(smem);
    const uint32_t sB = sA + ASMEM;
    const uint32_t mbB = sA + MBAR_OFF;
    const int tid = threadIdx.x;
    const int wid = tid >> 5;
    const int lane = tid & 31;
    const int wm = wid >> 1;    // 0..3 (32 M rows)
    const int wn = wid & 1;     // 0..1 (32 N cols)
    const int m0 = blockIdx.x * BM;

    if (tid == 0) {
        MBARRIER_INIT(mbB + 0, 1);
        MBARRIER_INIT(mbB + 8, 1);
        MBARRIER_EXPECT_TX(mbB + 0, BBUF);
        bulk_cp(sB, (const char*)g_bsw, BBUF, mbB + 0);
    }

    // ---- build A tile in smem from pixels (fused patchify) ----
    {
        const int m = tid >> 1;
        const int half = tid & 1;
        const int mg = m0 + m;
        const int b = mg >> 6, p = mg & 63;
        const int r = p >> 3, c = p & 7;
        const float* pix = pixels + (size_t)b * 3 * 4096 + c * 8;
#pragma unroll
        for (int gi = 0; gi < 12; gi++) {
            int g = half * 12 + gi;
            int d0 = g * 8;
            int ch = d0 >> 6;
            int pr = (d0 & 63) >> 3;
            const float4* src = (const float4*)(pix + (size_t)ch * 4096 + (r * 8 + pr) * 64);
            float4 v0 = src[0], v1 = src[1];
            __half2 h0 = __floats2half2_rn(v0.x, v0.y);
            __half2 h1 = __floats2half2_rn(v0.z, v0.w);
            __half2 h2 = __floats2half2_rn(v1.x, v1.y);
            __half2 h3 = __floats2half2_rn(v1.z, v1.w);
            uint4 u;
            u.x = *(uint32_t*)&h0; u.y = *(uint32_t*)&h1;
            u.z = *(uint32_t*)&h2; u.w = *(uint32_t*)&h3;
            *(uint4*)(smem + m * AROWB + ((g ^ (m & 7)) * 16)) = u;
        }
    }
    __syncthreads();

    float acc[2][2][2][4];
#pragma unroll
    for (int a = 0; a < 2; a++)
#pragma unroll
        for (int b = 0; b < 2; b++)
#pragma unroll
            for (int c = 0; c < 2; c++)
#pragma unroll
                for (int d = 0; d < 4; d++) acc[a][b][c][d] = 0.0f;

    float b1[4], b2[4];
    int   i1[4];
#pragma unroll
    for (int s = 0; s < 4; s++) { b1[s] = -3.0e38f; b2[s] = -3.0e38f; i1[s] = 0; }

    const int krow_base = (lane & 7) + ((lane & 16) ? 8 : 0);

    for (int it = 0; it < NTILE; ++it) {
        const int slot = it & 1;
        if (it) __syncthreads();
        if (tid == 0 && it + 1 < NTILE) {
            MBARRIER_EXPECT_TX(mbB + (slot ^ 1) * 8, BBUF);
            bulk_cp(sB + (slot ^ 1) * BBUF,
                    (const char*)g_bsw + (size_t)(it + 1) * BBUF,
                    BBUF, mbB + (slot ^ 1) * 8);
        }
        MBARRIER_WAIT_PARITY(mbB + slot * 8, (it >> 1) & 1);

        const uint32_t bbuf = sB + slot * BBUF;

        uint32_t af[2][2][4], bf[2][2][4];
#pragma unroll
        for (int mm = 0; mm < 2; mm++) {
            int r = wm * 32 + mm * 16 + (lane & 15);
            int g = (lane >> 4);
            ldsm4(af[0][mm], sA + r * AROWB + ((g ^ (r & 7)) * 16));
        }
#pragma unroll
        for (int nn2 = 0; nn2 < 2; nn2++) {
            int krow = krow_base;
            int g = wn * 4 + nn2 * 2 + ((lane >> 3) & 1);
            ldsm4t(bf[0][nn2], bbuf + krow * 128 + ((g ^ (krow & 7)) * 16));
        }

#pragma unroll
        for (int kk = 0; kk < KSTEPS; kk++) {
            const int cur = kk & 1, nxt = cur ^ 1;
            if (kk + 1 < KSTEPS) {
                const int k2 = kk + 1;
#pragma unroll
                for (int mm = 0; mm < 2; mm++) {
                    int r = wm * 32 + mm * 16 + (lane & 15);
                    int g = k2 * 2 + (lane >> 4);
                    ldsm4(af[nxt][mm], sA + r * AROWB + ((g ^ (r & 7)) * 16));
                }
                const int kc2 = k2 >> 2, kl2 = k2 & 3;
#pragma unroll
                for (int nn2 = 0; nn2 < 2; nn2++) {
                    int krow = kl2 * 16 + krow_base;
                    int g = wn * 4 + nn2 * 2 + ((lane >> 3) & 1);
                    ldsm4t(bf[nxt][nn2],
                           bbuf + kc2 * 8192 + krow * 128 + ((g ^ (krow & 7)) * 16));
                }
            }
#pragma unroll
            for (int nn2 = 0; nn2 < 2; nn2++) {
#pragma unroll
                for (int mm = 0; mm < 2; mm++) {
                    mma16816(acc[mm][nn2][0], af[cur][mm], bf[cur][nn2][0], bf[cur][nn2][2]);
                    mma16816(acc[mm][nn2][1], af[cur][mm], bf[cur][nn2][1], bf[cur][nn2][3]);
                }
            }
        }

        // ---- fold into running top-2 (ascending codes) ----
        const int colb = it * BN + wn * 32 + 2 * (lane & 3);
#pragma unroll
        for (int s = 0; s < 4; s++) {
            const int mm = s >> 1, h = s & 1;
#pragma unroll
            for (int nn2 = 0; nn2 < 2; nn2++) {
#pragma unroll
                for (int hn = 0; hn < 2; hn++) {
                    int cb = colb + nn2 * 16 + hn * 8;
                    float v0 = acc[mm][nn2][hn][h * 2];
                    if (v0 > b1[s]) { b2[s] = b1[s]; b1[s] = v0; i1[s] = cb; }
                    else if (v0 > b2[s]) b2[s] = v0;
                    float v1 = acc[mm][nn2][hn][h * 2 + 1];
                    if (v1 > b1[s]) { b2[s] = b1[s]; b1[s] = v1; i1[s] = cb + 1; }
                    else if (v1 > b2[s]) b2[s] = v1;
                    acc[mm][nn2][hn][h * 2] = 0.0f;
                    acc[mm][nn2][hn][h * 2 + 1] = 0.0f;
                }
            }
        }
    }

    // ---- quad-lane merge ----
#pragma unroll
    for (int s = 0; s < 4; s++) {
#pragma unroll
        for (int ofs = 1; ofs <= 2; ofs <<= 1) {
            float w1 = __shfl_xor_sync(0xFFFFFFFFu, b1[s], ofs);
            float w2 = __shfl_xor_sync(0xFFFFFFFFu, b2[s], ofs);
            int   k1 = __shfl_xor_sync(0xFFFFFFFFu, i1[s], ofs);
            if (w1 > b1[s] || (w1 == b1[s] && k1 < i1[s])) {
                b2[s] = fmaxf(b1[s], w2); b1[s] = w1; i1[s] = k1;
            } else {
                b2[s] = fmaxf(b2[s], w1);
            }
        }
    }

    // ---- cross-warp reduction via smem (reuse B buffers) ----
    __syncthreads();
    float* rv1 = (float*)(smem + ASMEM);
    float* rv2 = rv1 + BM * 2;
    int*   ri1 = (int*)(rv2 + BM * 2);
    if ((lane & 3) == 0) {
#pragma unroll
        for (int s = 0; s < 4; s++) {
            int row = wm * 32 + (s >> 1) * 16 + (s & 1) * 8 + (lane >> 2);
            rv1[row * 2 + wn] = b1[s];
            rv2[row * 2 + wn] = b2[s];
            ri1[row * 2 + wn] = i1[s];
        }
    }
    __syncthreads();
    if (tid < BM) {
        float v1 = rv1[tid * 2], v2 = rv2[tid * 2];
        int   j1 = ri1[tid * 2];
        float w1 = rv1[tid * 2 + 1], w2 = rv2[tid * 2 + 1];
        int   k1 = ri1[tid * 2 + 1];
        if (w1 > v1 || (w1 == v1 && k1 < j1)) { v2 = fmaxf(v1, w2); v1 = w1; j1 = k1; }
        else v2 = fmaxf(v2, w1);
        int row = m0 + tid;
        g_indices[row] = j1;
        outI[row] = (float)j1;
        if (v1 - v2 < DELTA) {
            int s = atomicAdd(&g_nflag, 1);
            g_flagged[s] = row;
        }
    }
}

// ===========================================================================
// 3a) Batch rescore: 16 code-slices x 16 flagged rows per item; 8 interleaved
//     sequential fp32 chains per thread (2 ascending batches of 8).
//     Per-code dots bit-identical; first-occurrence preserved everywhere.
// ===========================================================================
__global__ __launch_bounds__(256) void rescore_part_kernel(
    const float* __restrict__ pixels, const float* __restrict__ cb)
{
    __shared__ float4 sp[48][20];
    __shared__ float  rv[16][16];
    __shared__ int    ri[16][16];
    const int nf = g_nflag;
    if (nf == 0) return;
    const int ngroups = (nf + 15) >> 4;
    const int nitems = ngroups * NSLICE;
    const int tid = threadIdx.x;
    const int r = tid & 15;
    const int cl = tid >> 4;
    const float4* pix4 = (const float4*)pixels;

    for (int item = blockIdx.x; item < nitems; item += gridDim.x) {
        const int g = item >> 4;
        const int s = item & (NSLICE - 1);
        __syncthreads();
        for (int i = tid; i < 16 * 48; i += 256) {
            int rr = i / 48, qq = i % 48;
            int f = g * 16 + rr;
            int m = g_flagged[(f < nf) ? f : (nf - 1)];
            int b = m >> 6, p = m & 63;
            int pr_ = (p >> 3), pc_ = (p & 7);
            int d0 = qq * 4;
            int ch = d0 >> 6, rem = d0 & 63;
            int prr = rem >> 3, pcc = rem & 7;
            sp[qq][rr] = pix4[((size_t)(b * 3 + ch) * 64 + pr_ * 8 + prr) * 16
                              + pc_ * 2 + (pcc >> 2)];
        }
        __syncthreads();

        float bv = -3.0e38f;
        int bi = 0;
        const int kb = s * 256 + cl * 16;
#pragma unroll
        for (int batch = 0; batch < 2; batch++) {
            const int k0 = kb + batch * 8;
            const float4* c0 = (const float4*)(cb + (size_t)(k0 + 0) * PD);
            const float4* c1 = (const float4*)(cb + (size_t)(k0 + 1) * PD);
            const float4* c2 = (const float4*)(cb + (size_t)(k0 + 2) * PD);
            const float4* c3 = (const float4*)(cb + (size_t)(k0 + 3) * PD);
            const float4* c4 = (const float4*)(cb + (size_t)(k0 + 4) * PD);
            const float4* c5 = (const float4*)(cb + (size_t)(k0 + 5) * PD);
            const float4* c6 = (const float4*)(cb + (size_t)(k0 + 6) * PD);
            const float4* c7 = (const float4*)(cb + (size_t)(k0 + 7) * PD);
            float a0 = 0.f, a1 = 0.f, a2 = 0.f, a3 = 0.f;
            float a4 = 0.f, a5 = 0.f, a6 = 0.f, a7 = 0.f;
#pragma unroll 2
            for (int q = 0; q < 48; q++) {
                float4 p4 = sp[q][r];
                float4 x0 = c0[q];
                a0 = fmaf(p4.x, x0.x, a0); a0 = fmaf(p4.y, x0.y, a0);
                a0 = fmaf(p4.z, x0.z, a0); a0 = fmaf(p4.w, x0.w, a0);
                float4 x1 = c1[q];
                a1 = fmaf(p4.x, x1.x, a1); a1 = fmaf(p4.y, x1.y, a1);
                a1 = fmaf(p4.z, x1.z, a1); a1 = fmaf(p4.w, x1.w, a1);
                float4 x2 = c2[q];
                a2 = fmaf(p4.x, x2.x, a2); a2 = fmaf(p4.y, x2.y, a2);
                a2 = fmaf(p4.z, x2.z, a2); a2 = fmaf(p4.w, x2.w, a2);
                float4 x3 = c3[q];
                a3 = fmaf(p4.x, x3.x, a3); a3 = fmaf(p4.y, x3.y, a3);
                a3 = fmaf(p4.z, x3.z, a3); a3 = fmaf(p4.w, x3.w, a3);
                float4 x4 = c4[q];
                a4 = fmaf(p4.x, x4.x, a4); a4 = fmaf(p4.y, x4.y, a4);
                a4 = fmaf(p4.z, x4.z, a4); a4 = fmaf(p4.w, x4.w, a4);
                float4 x5 = c5[q];
                a5 = fmaf(p4.x, x5.x, a5); a5 = fmaf(p4.y, x5.y, a5);
                a5 = fmaf(p4.z, x5.z, a5); a5 = fmaf(p4.w, x5.w, a5);
                float4 x6 = c6[q];
                a6 = fmaf(p4.x, x6.x, a6); a6 = fmaf(p4.y, x6.y, a6);
                a6 = fmaf(p4.z, x6.z, a6); a6 = fmaf(p4.w, x6.w, a6);
                float4 x7 = c7[q];
                a7 = fmaf(p4.x, x7.x, a7); a7 = fmaf(p4.y, x7.y, a7);
                a7 = fmaf(p4.z, x7.z, a7); a7 = fmaf(p4.w, x7.w, a7);
            }
            // ascending code order -> strict '>' keeps first occurrence
            if (a0 > bv) { bv = a0; bi = k0; }
            if (a1 > bv) { bv = a1; bi = k0 + 1; }
            if (a2 > bv) { bv = a2; bi = k0 + 2; }
            if (a3 > bv) { bv = a3; bi = k0 + 3; }
            if (a4 > bv) { bv = a4; bi = k0 + 4; }
            if (a5 > bv) { bv = a5; bi = k0 + 5; }
            if (a6 > bv) { bv = a6; bi = k0 + 6; }
            if (a7 > bv) { bv = a7; bi = k0 + 7; }
        }
        rv[r][cl] = bv;
        ri[r][cl] = bi;
        __syncthreads();
        if (tid < 16) {
            float v = rv[tid][0];
            int ix = ri[tid][0];
#pragma unroll
            for (int t = 1; t < 16; t++) {
                float w = rv[tid][t];
                int k1 = ri[tid][t];
                if (w > v || (w == v && k1 < ix)) { v = w; ix = k1; }
            }
            int f = g * 16 + tid;
            if (f < nf) {
                g_part_val[(size_t)f * NSLICE + s] = v;
                g_part_idx[(size_t)f * NSLICE + s] = ix;
            }
        }
    }
}

// 3b) Combine slices (ascending s -> lowest-index tiebreak globally).
__global__ void rescore_combine_kernel(float* __restrict__ outI) {
    int f = blockIdx.x * blockDim.x + threadIdx.x;
    if (f >= g_nflag) return;
    float bv = g_part_val[(size_t)f * NSLICE];
    int bi = g_part_idx[(size_t)f * NSLICE];
#pragma unroll
    for (int s = 1; s < NSLICE; s++) {
        float v = g_part_val[(size_t)f * NSLICE + s];
        int ix = g_part_idx[(size_t)f * NSLICE + s];
        if (v > bv || (v == bv && ix < bi)) { bv = v; bi = ix; }
    }
    int m = g_flagged[f];
    g_indices[m] = bi;
    outI[m] = (float)bi;
}

// ===========================================================================
// 4) Fused tail: embed means (y=0,1) + VSA (y=2).
// ===========================================================================
__global__ __launch_bounds__(256) void tail_kernel(
    const float* __restrict__ emb, const float* __restrict__ cbv,
    const float* __restrict__ roles,
    float* __restrict__ outR, float* __restrict__ outL, float* __restrict__ outV)
{
    const int b = blockIdx.x;
    if (blockIdx.y < 2) {
        __shared__ int sIdx[NP];
        if (threadIdx.x < NP) sIdx[threadIdx.x] = g_indices[b * NP + threadIdx.x];
        __syncthreads();
        const int e4 = blockIdx.y * 256 + threadIdx.x;
        const float4* emb4 = (const float4*)emb;
        float4 s = make_float4(0.f, 0.f, 0.f, 0.f);
        float4 sl = make_float4(0.f, 0.f, 0.f, 0.f);
#pragma unroll 8
        for (int p = 0; p < NP; p++) {
            float4 v = emb4[(size_t)sIdx[p] * (ED / 4) + e4];
            s.x += v.x; s.y += v.y; s.z += v.z; s.w += v.w;
            int r = p >> 3, c = p & 7;
            if (r >= 3 && r < 6 && c >= 3 && c < 6) {
                sl.x += v.x; sl.y += v.y; sl.z += v.z; sl.w += v.w;
            }
        }
        const float iR = 1.0f / 64.0f, iL = 1.0f / 9.0f;
        ((float4*)outR)[(size_t)b * (ED / 4) + e4] =
            make_float4(s.x * iR, s.y * iR, s.z * iR, s.w * iR);
        ((float4*)outL)[(size_t)b * (ED / 4) + e4] =
            make_float4(sl.x * iL, sl.y * iL, sl.z * iL, sl.w * iL);
    } else {
        __shared__ int vIdx[16];
        __shared__ int vPos[16];
        if (threadIdx.x < 16) {
            int r = 2 + (threadIdx.x >> 2);
            int c = 2 + (threadIdx.x & 3);
            int p = r * 8 + c;
            vPos[threadIdx.x] = p;
            vIdx[threadIdx.x] = g_indices[b * NP + p];
        }
        __syncthreads();
        const float4* cbv4 = (const float4*)cbv;
        const float4* rol4 = (const float4*)roles;
#pragma unroll
        for (int half = 0; half < 2; half++) {
            const int v4 = half * 256 + threadIdx.x;
            int cx = 0, cy = 0, cz = 0, cw = 0;
#pragma unroll
            for (int t = 0; t < 16; t++) {
                float4 a = cbv4[(size_t)vIdx[t] * (VD / 4) + v4];
                float4 q = rol4[(size_t)vPos[t] * (VD / 4) + v4];
                cx += (a.x != q.x); cy += (a.y != q.y);
                cz += (a.z != q.z); cw += (a.w != q.w);
            }
            ((float4*)outV)[(size_t)b * (VD / 4) + v4] =
                make_float4(cx > 8 ? 1.f : 0.f, cy > 8 ? 1.f : 0.f,
                            cz > 8 ? 1.f : 0.f, cw > 8 ? 1.f : 0.f);
        }
    }
}

// ===========================================================================
extern "C" void kernel_launch(void* const* d_in, const int* in_sizes, int n_in,
                              void* d_out, int out_size)
{
    const float* pixels     = (const float*)d_in[0];
    const float* codebook   = (const float*)d_in[1];
    const float* embeddings = (const float*)d_in[2];
    const float* cbv        = (const float*)d_in[3];
    const float* roles      = (const float*)d_in[4];

    float* out  = (float*)d_out;
    float* outR = out;
    float* outV = out + (size_t)BATCH * ED;
    float* outI = out + 2 * (size_t)BATCH * ED;
    float* outL = out + 2 * (size_t)BATCH * ED + (size_t)BATCH * NP;

    static bool attr_set = false;
    if (!attr_set) {
        cudaFuncSetAttribute(gemm_mma_kernel,
                             cudaFuncAttributeMaxDynamicSharedMemorySize, GEMM_SMEM);
        attr_set = true;
    }

    prep_kernel<<<CB_BLOCKS + 1, 256>>>(codebook);
    gemm_mma_kernel<<<MROWS / BM, GEMM_THREADS, GEMM_SMEM>>>(pixels, outI);
    rescore_part_kernel<<<2048, 256>>>(pixels, codebook);
    rescore_combine_kernel<<<MROWS / 256, 256>>>(outI);
    tail_kernel<<<dim3(BATCH, 3), 256>>>(embeddings, cbv, roles, outR, outL, outV);
}

// round 17
// speedup vs baseline: 1.4053x; 1.0071x over previous
#include <cuda_runtime.h>
#include <cuda_fp16.h>
#include <cstdint>

// ===========================================================================
// VQPatchEncoder — single-term fp16 mma.sync GEMM + DELTA-certified exact
// argmax. R17: GEMM tile ring converted to producer/consumer mbarriers
// (full = tx, empty = 8 warp arrivals) — no CTA-wide __syncthreads in the
// mainloop, warps decorrelate across tile boundaries. Rescore/tail = R16.
// ===========================================================================

#define BATCH 1024
#define NP    64
#define PD    192
#define KC    4096
#define ED    2048
#define VD    2048
#define MROWS (BATCH * NP)      // 65536
#define BM    128
#define BN    64
#define NTILE  (KC / BN)         // 64
#define KSTEPS (PD / 16)         // 12
#define AROWB  (PD * 2)          // 384
#define ASMEM  (BM * AROWB)      // 49152
#define BBUF   (PD * BN * 2)     // 24576 (full-K tile)
#define MBAR_OFF (ASMEM + 2 * BBUF)           // 98304
#define GEMM_SMEM (MBAR_OFF + 64)             // 98368
#define GEMM_THREADS 256
#define DELTA 4e-3f
#define NSLICE 16                 // rescore code slices (256 codes each)

// ---- device-global scratch ------------------------------------------------
__device__ __align__(16) __half g_bsw[(size_t)PD * KC];   // per-tile smem images
__device__ int    g_indices[MROWS];
__device__ int    g_flagged[MROWS];
__device__ int    g_nflag;
__device__ float  g_part_val[(size_t)MROWS * NSLICE];  // rescore partials
__device__ int    g_part_idx[(size_t)MROWS * NSLICE];

__device__ __forceinline__ uint32_t smem_u32(const void* p) {
    uint32_t a;
    asm("{ .reg .u64 t; cvta.to.shared.u64 t, %1; cvt.u32.u64 %0, t; }"
        : "=r"(a) : "l"(p));
    return a;
}

#define MBARRIER_INIT(mbar, cnt) \
    asm volatile("mbarrier.init.shared.b64 [%0], %1;" \
                 :: "r"((uint32_t)(mbar)), "r"((uint32_t)(cnt)) : "memory")
#define MBARRIER_EXPECT_TX(mbar, bytes) \
    asm volatile("mbarrier.arrive.expect_tx.shared.b64 _, [%0], %1;" \
                 :: "r"((uint32_t)(mbar)), "r"((uint32_t)(bytes)) : "memory")
#define MBARRIER_ARRIVE(mbar) \
    asm volatile("mbarrier.arrive.shared.b64 _, [%0];" \
                 :: "r"((uint32_t)(mbar)) : "memory")

#define MBARRIER_WAIT_PARITY(mbar_addr, phase_parity) do {                        \
    uint32_t _mbar = (uint32_t)(mbar_addr);                                       \
    uint32_t _par  = (uint32_t)(phase_parity);                                    \
    uint32_t _done;                                                               \
    asm volatile("{\n\t.reg .pred p;\n\t"                                         \
        "mbarrier.try_wait.parity.acquire.cta.shared::cta.b64 p, [%1], %2;\n\t"   \
        "selp.b32 %0, 1, 0, p;\n\t}"                                              \
        : "=r"(_done) : "r"(_mbar), "r"(_par) : "memory");                        \
    if (!_done) {                                                                 \
        asm volatile("{\n\t.reg .pred P1;\n\t"                                    \
            "WAIT_LOOP_%=:\n\t"                                                   \
            "mbarrier.try_wait.parity.acquire.cta.shared::cta.b64 P1, [%0], %1, 0x989680;\n\t" \
            "@P1 bra.uni WAIT_DONE_%=;\n\t"                                       \
            "bra.uni WAIT_LOOP_%=;\n\t"                                           \
            "WAIT_DONE_%=:\n\t}"                                                  \
            :: "r"(_mbar), "r"(_par) : "memory");                                 \
    }                                                                             \
} while (0)

__device__ __forceinline__ void bulk_cp(uint32_t dst, const void* src,
                                        uint32_t bytes, uint32_t mbar) {
    asm volatile(
        "cp.async.bulk.shared::cta.global.mbarrier::complete_tx::bytes "
        "[%0], [%1], %2, [%3];"
        :: "r"(dst), "l"(src), "r"(bytes), "r"(mbar) : "memory");
}

__device__ __forceinline__ void ldsm4(uint32_t* r, uint32_t addr) {
    asm volatile("ldmatrix.sync.aligned.m8n8.x4.shared.b16 {%0,%1,%2,%3}, [%4];"
                 : "=r"(r[0]), "=r"(r[1]), "=r"(r[2]), "=r"(r[3]) : "r"(addr));
}
__device__ __forceinline__ void ldsm4t(uint32_t* r, uint32_t addr) {
    asm volatile("ldmatrix.sync.aligned.m8n8.x4.trans.shared.b16 {%0,%1,%2,%3}, [%4];"
                 : "=r"(r[0]), "=r"(r[1]), "=r"(r[2]), "=r"(r[3]) : "r"(addr));
}
__device__ __forceinline__ void mma16816(float* c, const uint32_t* a,
                                         uint32_t b0, uint32_t b1) {
    asm volatile(
        "mma.sync.aligned.m16n8k16.row.col.f32.f16.f16.f32 "
        "{%0,%1,%2,%3}, {%4,%5,%6,%7}, {%8,%9}, {%0,%1,%2,%3};"
        : "+f"(c[0]), "+f"(c[1]), "+f"(c[2]), "+f"(c[3])
        : "r"(a[0]), "r"(a[1]), "r"(a[2]), "r"(a[3]), "r"(b0), "r"(b1));
}

// ===========================================================================
// 1) Prep: codebook smem-image layout + flag reset only.
// ===========================================================================
#define CB_BLOCKS  ((PD * KC) / 256)             // 3072
__global__ void prep_kernel(const float* __restrict__ cbk) {
    int bid = blockIdx.x;
    if (bid < CB_BLOCKS) {
        int idx = bid * 256 + threadIdx.x;
        int n = idx % KC;
        int d = idx / KC;
        int t = n >> 6, nt = n & 63;
        int kc = d >> 6, r = d & 63;
        int g = nt >> 3;
        size_t half_off = (size_t)(t * 3 + kc) * 4096
                        + r * 64 + ((g ^ (r & 7)) * 8) + (nt & 7);
        g_bsw[half_off] = __float2half_rn(cbk[(size_t)n * PD + d]);
    } else {
        if (threadIdx.x == 0) g_nflag = 0;
    }
}

// ===========================================================================
// 2) fp16 mma.sync GEMM + fused top-2 argmax.
//    Barriers at MBAR_OFF: full0(+0), full1(+8), empty0(+16), empty1(+24).
//    full: tx-based (count 1); empty: 8 warp arrivals. Only tid 0 waits on
//    empty before refilling a slot; other warps drift one tile ahead.
// ===========================================================================
__global__ __launch_bounds__(GEMM_THREADS, 2) void gemm_mma_kernel(
    const float* __restrict__ pixels, float* __restrict__ outI)
{
    extern __shared__ char smem[];
    const uint32_t sA = smem_u32(smem);
    const uint32_t sB = sA + ASMEM;
    const uint32_t mbF = sA + MBAR_OFF;        // full[2]
    const uint32_t mbE = sA + MBAR_OFF + 16;   // empty[2]
    const int tid = threadIdx.x;
    const int wid = tid >> 5;
    const int lane = tid & 31;
    const int wm = wid >> 1;    // 0..3 (32 M rows)
    const int wn = wid & 1;     // 0..1 (32 N cols)
    const int m0 = blockIdx.x * BM;

    if (tid == 0) {
        MBARRIER_INIT(mbF + 0, 1);
        MBARRIER_INIT(mbF + 8, 1);
        MBARRIER_INIT(mbE + 0, 8);
        MBARRIER_INIT(mbE + 8, 8);
        MBARRIER_EXPECT_TX(mbF + 0, BBUF);
        bulk_cp(sB, (const char*)g_bsw, BBUF, mbF + 0);
        MBARRIER_EXPECT_TX(mbF + 8, BBUF);
        bulk_cp(sB + BBUF, (const char*)g_bsw + BBUF, BBUF, mbF + 8);
    }

    // ---- build A tile in smem from pixels (fused patchify) ----
    {
        const int m = tid >> 1;
        const int half = tid & 1;
        const int mg = m0 + m;
        const int b = mg >> 6, p = mg & 63;
        const int r = p >> 3, c = p & 7;
        const float* pix = pixels + (size_t)b * 3 * 4096 + c * 8;
#pragma unroll
        for (int gi = 0; gi < 12; gi++) {
            int g = half * 12 + gi;
            int d0 = g * 8;
            int ch = d0 >> 6;
            int pr = (d0 & 63) >> 3;
            const float4* src = (const float4*)(pix + (size_t)ch * 4096 + (r * 8 + pr) * 64);
            float4 v0 = src[0], v1 = src[1];
            __half2 h0 = __floats2half2_rn(v0.x, v0.y);
            __half2 h1 = __floats2half2_rn(v0.z, v0.w);
            __half2 h2 = __floats2half2_rn(v1.x, v1.y);
            __half2 h3 = __floats2half2_rn(v1.z, v1.w);
            uint4 u;
            u.x = *(uint32_t*)&h0; u.y = *(uint32_t*)&h1;
            u.z = *(uint32_t*)&h2; u.w = *(uint32_t*)&h3;
            *(uint4*)(smem + m * AROWB + ((g ^ (m & 7)) * 16)) = u;
        }
    }
    __syncthreads();   // A ready + barrier init visible

    float acc[2][2][2][4];
#pragma unroll
    for (int a = 0; a < 2; a++)
#pragma unroll
        for (int b = 0; b < 2; b++)
#pragma unroll
            for (int c = 0; c < 2; c++)
#pragma unroll
                for (int d = 0; d < 4; d++) acc[a][b][c][d] = 0.0f;

    float b1[4], b2[4];
    int   i1[4];
#pragma unroll
    for (int s = 0; s < 4; s++) { b1[s] = -3.0e38f; b2[s] = -3.0e38f; i1[s] = 0; }

    const int krow_base = (lane & 7) + ((lane & 16) ? 8 : 0);

    for (int it = 0; it < NTILE; ++it) {
        const int slot = it & 1;
        const int phase = (it >> 1) & 1;
        MBARRIER_WAIT_PARITY(mbF + slot * 8, phase);

        const uint32_t bbuf = sB + slot * BBUF;

        uint32_t af[2][2][4], bf[2][2][4];
#pragma unroll
        for (int mm = 0; mm < 2; mm++) {
            int r = wm * 32 + mm * 16 + (lane & 15);
            int g = (lane >> 4);
            ldsm4(af[0][mm], sA + r * AROWB + ((g ^ (r & 7)) * 16));
        }
#pragma unroll
        for (int nn2 = 0; nn2 < 2; nn2++) {
            int krow = krow_base;
            int g = wn * 4 + nn2 * 2 + ((lane >> 3) & 1);
            ldsm4t(bf[0][nn2], bbuf + krow * 128 + ((g ^ (krow & 7)) * 16));
        }

#pragma unroll
        for (int kk = 0; kk < KSTEPS; kk++) {
            const int cur = kk & 1, nxt = cur ^ 1;
            if (kk + 1 < KSTEPS) {
                const int k2 = kk + 1;
#pragma unroll
                for (int mm = 0; mm < 2; mm++) {
                    int r = wm * 32 + mm * 16 + (lane & 15);
                    int g = k2 * 2 + (lane >> 4);
                    ldsm4(af[nxt][mm], sA + r * AROWB + ((g ^ (r & 7)) * 16));
                }
                const int kc2 = k2 >> 2, kl2 = k2 & 3;
#pragma unroll
                for (int nn2 = 0; nn2 < 2; nn2++) {
                    int krow = kl2 * 16 + krow_base;
                    int g = wn * 4 + nn2 * 2 + ((lane >> 3) & 1);
                    ldsm4t(bf[nxt][nn2],
                           bbuf + kc2 * 8192 + krow * 128 + ((g ^ (krow & 7)) * 16));
                }
            }
#pragma unroll
            for (int nn2 = 0; nn2 < 2; nn2++) {
#pragma unroll
                for (int mm = 0; mm < 2; mm++) {
                    mma16816(acc[mm][nn2][0], af[cur][mm], bf[cur][nn2][0], bf[cur][nn2][2]);
                    mma16816(acc[mm][nn2][1], af[cur][mm], bf[cur][nn2][1], bf[cur][nn2][3]);
                }
            }
        }

        // ---- this warp is done reading slot: release it ----
        if (lane == 0) MBARRIER_ARRIVE(mbE + slot * 8);

        // ---- producer: refill slot with tile it+2 once all 8 warps arrive ----
        if (tid == 0 && it + 2 < NTILE) {
            MBARRIER_WAIT_PARITY(mbE + slot * 8, phase);
            MBARRIER_EXPECT_TX(mbF + slot * 8, BBUF);
            bulk_cp(sB + slot * BBUF,
                    (const char*)g_bsw + (size_t)(it + 2) * BBUF,
                    BBUF, mbF + slot * 8);
        }

        // ---- fold into running top-2 (ascending codes) ----
        const int colb = it * BN + wn * 32 + 2 * (lane & 3);
#pragma unroll
        for (int s = 0; s < 4; s++) {
            const int mm = s >> 1, h = s & 1;
#pragma unroll
            for (int nn2 = 0; nn2 < 2; nn2++) {
#pragma unroll
                for (int hn = 0; hn < 2; hn++) {
                    int cb = colb + nn2 * 16 + hn * 8;
                    float v0 = acc[mm][nn2][hn][h * 2];
                    if (v0 > b1[s]) { b2[s] = b1[s]; b1[s] = v0; i1[s] = cb; }
                    else if (v0 > b2[s]) b2[s] = v0;
                    float v1 = acc[mm][nn2][hn][h * 2 + 1];
                    if (v1 > b1[s]) { b2[s] = b1[s]; b1[s] = v1; i1[s] = cb + 1; }
                    else if (v1 > b2[s]) b2[s] = v1;
                    acc[mm][nn2][hn][h * 2] = 0.0f;
                    acc[mm][nn2][hn][h * 2 + 1] = 0.0f;
                }
            }
        }
    }

    // ---- quad-lane merge ----
#pragma unroll
    for (int s = 0; s < 4; s++) {
#pragma unroll
        for (int ofs = 1; ofs <= 2; ofs <<= 1) {
            float w1 = __shfl_xor_sync(0xFFFFFFFFu, b1[s], ofs);
            float w2 = __shfl_xor_sync(0xFFFFFFFFu, b2[s], ofs);
            int   k1 = __shfl_xor_sync(0xFFFFFFFFu, i1[s], ofs);
            if (w1 > b1[s] || (w1 == b1[s] && k1 < i1[s])) {
                b2[s] = fmaxf(b1[s], w2); b1[s] = w1; i1[s] = k1;
            } else {
                b2[s] = fmaxf(b2[s], w1);
            }
        }
    }

    // ---- cross-warp reduction via smem (reuse B buffers) ----
    __syncthreads();
    float* rv1 = (float*)(smem + ASMEM);
    float* rv2 = rv1 + BM * 2;
    int*   ri1 = (int*)(rv2 + BM * 2);
    if ((lane & 3) == 0) {
#pragma unroll
        for (int s = 0; s < 4; s++) {
            int row = wm * 32 + (s >> 1) * 16 + (s & 1) * 8 + (lane >> 2);
            rv1[row * 2 + wn] = b1[s];
            rv2[row * 2 + wn] = b2[s];
            ri1[row * 2 + wn] = i1[s];
        }
    }
    __syncthreads();
    if (tid < BM) {
        float v1 = rv1[tid * 2], v2 = rv2[tid * 2];
        int   j1 = ri1[tid * 2];
        float w1 = rv1[tid * 2 + 1], w2 = rv2[tid * 2 + 1];
        int   k1 = ri1[tid * 2 + 1];
        if (w1 > v1 || (w1 == v1 && k1 < j1)) { v2 = fmaxf(v1, w2); v1 = w1; j1 = k1; }
        else v2 = fmaxf(v2, w1);
        int row = m0 + tid;
        g_indices[row] = j1;
        outI[row] = (float)j1;
        if (v1 - v2 < DELTA) {
            int s = atomicAdd(&g_nflag, 1);
            g_flagged[s] = row;
        }
    }
}

// ===========================================================================
// 3a) Batch rescore (R16): 16 code-slices x 16 flagged rows per item;
//     8 interleaved sequential fp32 chains per thread.
// ===========================================================================
__global__ __launch_bounds__(256) void rescore_part_kernel(
    const float* __restrict__ pixels, const float* __restrict__ cb)
{
    __shared__ float4 sp[48][20];
    __shared__ float  rv[16][16];
    __shared__ int    ri[16][16];
    const int nf = g_nflag;
    if (nf == 0) return;
    const int ngroups = (nf + 15) >> 4;
    const int nitems = ngroups * NSLICE;
    const int tid = threadIdx.x;
    const int r = tid & 15;
    const int cl = tid >> 4;
    const float4* pix4 = (const float4*)pixels;

    for (int item = blockIdx.x; item < nitems; item += gridDim.x) {
        const int g = item >> 4;
        const int s = item & (NSLICE - 1);
        __syncthreads();
        for (int i = tid; i < 16 * 48; i += 256) {
            int rr = i / 48, qq = i % 48;
            int f = g * 16 + rr;
            int m = g_flagged[(f < nf) ? f : (nf - 1)];
            int b = m >> 6, p = m & 63;
            int pr_ = (p >> 3), pc_ = (p & 7);
            int d0 = qq * 4;
            int ch = d0 >> 6, rem = d0 & 63;
            int prr = rem >> 3, pcc = rem & 7;
            sp[qq][rr] = pix4[((size_t)(b * 3 + ch) * 64 + pr_ * 8 + prr) * 16
                              + pc_ * 2 + (pcc >> 2)];
        }
        __syncthreads();

        float bv = -3.0e38f;
        int bi = 0;
        const int kb = s * 256 + cl * 16;
#pragma unroll
        for (int batch = 0; batch < 2; batch++) {
            const int k0 = kb + batch * 8;
            const float4* c0 = (const float4*)(cb + (size_t)(k0 + 0) * PD);
            const float4* c1 = (const float4*)(cb + (size_t)(k0 + 1) * PD);
            const float4* c2 = (const float4*)(cb + (size_t)(k0 + 2) * PD);
            const float4* c3 = (const float4*)(cb + (size_t)(k0 + 3) * PD);
            const float4* c4 = (const float4*)(cb + (size_t)(k0 + 4) * PD);
            const float4* c5 = (const float4*)(cb + (size_t)(k0 + 5) * PD);
            const float4* c6 = (const float4*)(cb + (size_t)(k0 + 6) * PD);
            const float4* c7 = (const float4*)(cb + (size_t)(k0 + 7) * PD);
            float a0 = 0.f, a1 = 0.f, a2 = 0.f, a3 = 0.f;
            float a4 = 0.f, a5 = 0.f, a6 = 0.f, a7 = 0.f;
#pragma unroll 2
            for (int q = 0; q < 48; q++) {
                float4 p4 = sp[q][r];
                float4 x0 = c0[q];
                a0 = fmaf(p4.x, x0.x, a0); a0 = fmaf(p4.y, x0.y, a0);
                a0 = fmaf(p4.z, x0.z, a0); a0 = fmaf(p4.w, x0.w, a0);
                float4 x1 = c1[q];
                a1 = fmaf(p4.x, x1.x, a1); a1 = fmaf(p4.y, x1.y, a1);
                a1 = fmaf(p4.z, x1.z, a1); a1 = fmaf(p4.w, x1.w, a1);
                float4 x2 = c2[q];
                a2 = fmaf(p4.x, x2.x, a2); a2 = fmaf(p4.y, x2.y, a2);
                a2 = fmaf(p4.z, x2.z, a2); a2 = fmaf(p4.w, x2.w, a2);
                float4 x3 = c3[q];
                a3 = fmaf(p4.x, x3.x, a3); a3 = fmaf(p4.y, x3.y, a3);
                a3 = fmaf(p4.z, x3.z, a3); a3 = fmaf(p4.w, x3.w, a3);
                float4 x4 = c4[q];
                a4 = fmaf(p4.x, x4.x, a4); a4 = fmaf(p4.y, x4.y, a4);
                a4 = fmaf(p4.z, x4.z, a4); a4 = fmaf(p4.w, x4.w, a4);
                float4 x5 = c5[q];
                a5 = fmaf(p4.x, x5.x, a5); a5 = fmaf(p4.y, x5.y, a5);
                a5 = fmaf(p4.z, x5.z, a5); a5 = fmaf(p4.w, x5.w, a5);
                float4 x6 = c6[q];
                a6 = fmaf(p4.x, x6.x, a6); a6 = fmaf(p4.y, x6.y, a6);
                a6 = fmaf(p4.z, x6.z, a6); a6 = fmaf(p4.w, x6.w, a6);
                float4 x7 = c7[q];
                a7 = fmaf(p4.x, x7.x, a7); a7 = fmaf(p4.y, x7.y, a7);
                a7 = fmaf(p4.z, x7.z, a7); a7 = fmaf(p4.w, x7.w, a7);
            }
            if (a0 > bv) { bv = a0; bi = k0; }
            if (a1 > bv) { bv = a1; bi = k0 + 1; }
            if (a2 > bv) { bv = a2; bi = k0 + 2; }
            if (a3 > bv) { bv = a3; bi = k0 + 3; }
            if (a4 > bv) { bv = a4; bi = k0 + 4; }
            if (a5 > bv) { bv = a5; bi = k0 + 5; }
            if (a6 > bv) { bv = a6; bi = k0 + 6; }
            if (a7 > bv) { bv = a7; bi = k0 + 7; }
        }
        rv[r][cl] = bv;
        ri[r][cl] = bi;
        __syncthreads();
        if (tid < 16) {
            float v = rv[tid][0];
            int ix = ri[tid][0];
#pragma unroll
            for (int t = 1; t < 16; t++) {
                float w = rv[tid][t];
                int k1 = ri[tid][t];
                if (w > v || (w == v && k1 < ix)) { v = w; ix = k1; }
            }
            int f = g * 16 + tid;
            if (f < nf) {
                g_part_val[(size_t)f * NSLICE + s] = v;
                g_part_idx[(size_t)f * NSLICE + s] = ix;
            }
        }
    }
}

// 3b) Combine slices (ascending s -> lowest-index tiebreak globally).
__global__ void rescore_combine_kernel(float* __restrict__ outI) {
    int f = blockIdx.x * blockDim.x + threadIdx.x;
    if (f >= g_nflag) return;
    float bv = g_part_val[(size_t)f * NSLICE];
    int bi = g_part_idx[(size_t)f * NSLICE];
#pragma unroll
    for (int s = 1; s < NSLICE; s++) {
        float v = g_part_val[(size_t)f * NSLICE + s];
        int ix = g_part_idx[(size_t)f * NSLICE + s];
        if (v > bv || (v == bv && ix < bi)) { bv = v; bi = ix; }
    }
    int m = g_flagged[f];
    g_indices[m] = bi;
    outI[m] = (float)bi;
}

// ===========================================================================
// 4) Fused tail: embed means (y=0,1) + VSA (y=2).
// ===========================================================================
__global__ __launch_bounds__(256) void tail_kernel(
    const float* __restrict__ emb, const float* __restrict__ cbv,
    const float* __restrict__ roles,
    float* __restrict__ outR, float* __restrict__ outL, float* __restrict__ outV)
{
    const int b = blockIdx.x;
    if (blockIdx.y < 2) {
        __shared__ int sIdx[NP];
        if (threadIdx.x < NP) sIdx[threadIdx.x] = g_indices[b * NP + threadIdx.x];
        __syncthreads();
        const int e4 = blockIdx.y * 256 + threadIdx.x;
        const float4* emb4 = (const float4*)emb;
        float4 s = make_float4(0.f, 0.f, 0.f, 0.f);
        float4 sl = make_float4(0.f, 0.f, 0.f, 0.f);
#pragma unroll 8
        for (int p = 0; p < NP; p++) {
            float4 v = emb4[(size_t)sIdx[p] * (ED / 4) + e4];
            s.x += v.x; s.y += v.y; s.z += v.z; s.w += v.w;
            int r = p >> 3, c = p & 7;
            if (r >= 3 && r < 6 && c >= 3 && c < 6) {
                sl.x += v.x; sl.y += v.y; sl.z += v.z; sl.w += v.w;
            }
        }
        const float iR = 1.0f / 64.0f, iL = 1.0f / 9.0f;
        ((float4*)outR)[(size_t)b * (ED / 4) + e4] =
            make_float4(s.x * iR, s.y * iR, s.z * iR, s.w * iR);
        ((float4*)outL)[(size_t)b * (ED / 4) + e4] =
            make_float4(sl.x * iL, sl.y * iL, sl.z * iL, sl.w * iL);
    } else {
        __shared__ int vIdx[16];
        __shared__ int vPos[16];
        if (threadIdx.x < 16) {
            int r = 2 + (threadIdx.x >> 2);
            int c = 2 + (threadIdx.x & 3);
            int p = r * 8 + c;
            vPos[threadIdx.x] = p;
            vIdx[threadIdx.x] = g_indices[b * NP + p];
        }
        __syncthreads();
        const float4* cbv4 = (const float4*)cbv;
        const float4* rol4 = (const float4*)roles;
#pragma unroll
        for (int half = 0; half < 2; half++) {
            const int v4 = half * 256 + threadIdx.x;
            int cx = 0, cy = 0, cz = 0, cw = 0;
#pragma unroll
            for (int t = 0; t < 16; t++) {
                float4 a = cbv4[(size_t)vIdx[t] * (VD / 4) + v4];
                float4 q = rol4[(size_t)vPos[t] * (VD / 4) + v4];
                cx += (a.x != q.x); cy += (a.y != q.y);
                cz += (a.z != q.z); cw += (a.w != q.w);
            }
            ((float4*)outV)[(size_t)b * (VD / 4) + v4] =
                make_float4(cx > 8 ? 1.f : 0.f, cy > 8 ? 1.f : 0.f,
                            cz > 8 ? 1.f : 0.f, cw > 8 ? 1.f : 0.f);
        }
    }
}

// ===========================================================================
extern "C" void kernel_launch(void* const* d_in, const int* in_sizes, int n_in,
                              void* d_out, int out_size)
{
    const float* pixels     = (const float*)d_in[0];
    const float* codebook   = (const float*)d_in[1];
    const float* embeddings = (const float*)d_in[2];
    const float* cbv        = (const float*)d_in[3];
    const float* roles      = (const float*)d_in[4];

    float* out  = (float*)d_out;
    float* outR = out;
    float* outV = out + (size_t)BATCH * ED;
    float* outI = out + 2 * (size_t)BATCH * ED;
    float* outL = out + 2 * (size_t)BATCH * ED + (size_t)BATCH * NP;

    static bool attr_set = false;
    if (!attr_set) {
        cudaFuncSetAttribute(gemm_mma_kernel,
                             cudaFuncAttributeMaxDynamicSharedMemorySize, GEMM_SMEM);
        attr_set = true;
    }

    prep_kernel<<<CB_BLOCKS + 1, 256>>>(codebook);
    gemm_mma_kernel<<<MROWS / BM, GEMM_THREADS, GEMM_SMEM>>>(pixels, outI);
    rescore_part_kernel<<<2048, 256>>>(pixels, codebook);
    rescore_combine_kernel<<<MROWS / 256, 256>>>(outI);
    tail_kernel<<<dim3(BATCH, 3), 256>>>(embeddings, cbv, roles, outR, outL, outV);
}